// round 1
// baseline (speedup 1.0000x reference)
#include <cuda_runtime.h>
#include <cstdint>

#define NMAX 50000
#define EMAX 800000
#define INDIM 128
#define ODIM 128      // HEADS * HEAD_DIM = 8*16
#define BM 64
#define HS 132        // padded h-tile stride (bank-conflict-free a-broadcasts)

// ---- device scratch (no cudaMalloc allowed) ----
__device__ float g_Q[NMAX * ODIM];          // Q[n][128]
__device__ float g_KV[NMAX * 2 * ODIM];     // per node: K[128] | V[128]
__device__ int   g_cnt[NMAX + 1];
__device__ int   g_row[NMAX + 1];
__device__ int   g_cur[NMAX];
__device__ int   g_srcs[EMAX];
__device__ int   g_bsum[64];
__device__ int   g_boff[64];

// ---- packed f32x2 helpers (sm_103a) ----
__device__ __forceinline__ unsigned long long pack2(float a) {
    unsigned long long r;
    asm("mov.b64 %0, {%1, %1};" : "=l"(r) : "f"(a));
    return r;
}
__device__ __forceinline__ void ffma2(unsigned long long& d,
                                      unsigned long long a, unsigned long long b) {
    asm("fma.rn.f32x2 %0, %1, %2, %0;" : "+l"(d) : "l"(a), "l"(b));
}
__device__ __forceinline__ float2 unpack2(unsigned long long p) {
    float2 f;
    asm("mov.b64 {%0, %1}, %2;" : "=f"(f.x), "=f"(f.y) : "l"(p));
    return f;
}

// ============================================================
// QKV projection: C[N,128] = h[N,128] @ W[128,128] + b
// blockIdx.y selects {WQ, WK, WV}; 64 nodes x 128 cols per CTA.
// f32x2 packed FMA: each thread computes a 4x8 microtile.
// ============================================================
__global__ void qkv_gemm(const float* __restrict__ h,
                         const float* __restrict__ WQ, const float* __restrict__ bQ,
                         const float* __restrict__ WK, const float* __restrict__ bK,
                         const float* __restrict__ WV, const float* __restrict__ bV,
                         int N) {
    extern __shared__ float smem[];
    float* h_s = smem;               // BM * HS
    float* w_s = smem + BM * HS;     // 128 * 128

    int m = blockIdx.y;
    const float* W    = (m == 0) ? WQ : (m == 1) ? WK : WV;
    const float* bias = (m == 0) ? bQ : (m == 1) ? bK : bV;
    int node0 = blockIdx.x * BM;
    int tid = threadIdx.x;

    // load h tile (zero-pad OOB rows)
    for (int i = tid; i < BM * 32; i += 256) {
        int r = i >> 5, c4 = i & 31;
        int n = node0 + r;
        float4 v = make_float4(0.f, 0.f, 0.f, 0.f);
        if (n < N) v = reinterpret_cast<const float4*>(h)[n * 32 + c4];
        *reinterpret_cast<float4*>(h_s + r * HS + c4 * 4) = v;
    }
    // load W tile (contiguous)
    for (int i = tid; i < 128 * 32; i += 256)
        reinterpret_cast<float4*>(w_s)[i] = reinterpret_cast<const float4*>(W)[i];
    __syncthreads();

    int tx = tid & 15, ty = tid >> 4;
    int c0 = tx * 8, r0 = ty * 4;

    unsigned long long acc[4][4];
#pragma unroll
    for (int i = 0; i < 4; i++)
#pragma unroll
        for (int j = 0; j < 4; j++) acc[i][j] = 0ULL;

#pragma unroll 4
    for (int k = 0; k < 128; k++) {
        ulonglong2 w0 = *reinterpret_cast<ulonglong2*>(w_s + k * 128 + c0);
        ulonglong2 w1 = *reinterpret_cast<ulonglong2*>(w_s + k * 128 + c0 + 4);
#pragma unroll
        for (int i = 0; i < 4; i++) {
            unsigned long long a2 = pack2(h_s[(r0 + i) * HS + k]);
            ffma2(acc[i][0], a2, w0.x);
            ffma2(acc[i][1], a2, w0.y);
            ffma2(acc[i][2], a2, w1.x);
            ffma2(acc[i][3], a2, w1.y);
        }
    }

    float4 b0 = *reinterpret_cast<const float4*>(bias + c0);
    float4 b1 = *reinterpret_cast<const float4*>(bias + c0 + 4);

#pragma unroll
    for (int i = 0; i < 4; i++) {
        int n = node0 + r0 + i;
        if (n >= N) continue;
        float* outp = (m == 0) ? (g_Q + (size_t)n * ODIM + c0)
                               : (g_KV + (size_t)n * 2 * ODIM + (m == 2 ? ODIM : 0) + c0);
        float2 p0 = unpack2(acc[i][0]), p1 = unpack2(acc[i][1]);
        float2 p2 = unpack2(acc[i][2]), p3 = unpack2(acc[i][3]);
        float4 o0 = make_float4(p0.x + b0.x, p0.y + b0.y, p1.x + b0.z, p1.y + b0.w);
        float4 o1 = make_float4(p2.x + b1.x, p2.y + b1.y, p3.x + b1.z, p3.y + b1.w);
        *reinterpret_cast<float4*>(outp) = o0;
        *reinterpret_cast<float4*>(outp + 4) = o1;
    }
}

// ============================================================
// CSR construction
// ============================================================
__global__ void zero_cnt(int N) {
    int i = blockIdx.x * 256 + threadIdx.x;
    if (i <= N) g_cnt[i] = 0;
}

__global__ void hist_k(const int* __restrict__ dst, int E) {
    int e = blockIdx.x * 256 + threadIdx.x;
    if (e < E) atomicAdd(&g_cnt[dst[e]], 1);
}

__global__ void scan_partial(int N) {
    __shared__ int s[1024];
    int tid = threadIdx.x;
    int idx = blockIdx.x * 1024 + tid;
    int x = (idx < N) ? g_cnt[idx] : 0;
    s[tid] = x;
    __syncthreads();
    for (int off = 1; off < 1024; off <<= 1) {
        int t = (tid >= off) ? s[tid - off] : 0;
        __syncthreads();
        if (tid >= off) s[tid] += t;
        __syncthreads();
    }
    if (idx < N) g_row[idx] = s[tid] - x;            // local exclusive
    if (tid == 1023) g_bsum[blockIdx.x] = s[1023];   // block total
}

__global__ void scan_mid(int nb, int N) {
    __shared__ int s[1024];
    int tid = threadIdx.x;
    int x = (tid < nb) ? g_bsum[tid] : 0;
    s[tid] = x;
    __syncthreads();
    for (int off = 1; off < 1024; off <<= 1) {
        int t = (tid >= off) ? s[tid - off] : 0;
        __syncthreads();
        if (tid >= off) s[tid] += t;
        __syncthreads();
    }
    if (tid < nb) g_boff[tid] = s[tid] - x;
    if (tid == nb - 1) g_row[N] = s[tid];            // grand total
}

__global__ void scan_add(int N) {
    int idx = blockIdx.x * 1024 + threadIdx.x;
    if (idx < N) {
        int v = g_row[idx] + g_boff[blockIdx.x];
        g_row[idx] = v;
        g_cur[idx] = v;
    }
}

__global__ void scatter_k(const int* __restrict__ src, const int* __restrict__ dst, int E) {
    int e = blockIdx.x * 256 + threadIdx.x;
    if (e < E) {
        int pos = atomicAdd(&g_cur[dst[e]], 1);
        g_srcs[pos] = src[e];
    }
}

// ============================================================
// Gather attention: one warp per dst node.
// Lane l handles head l>>2, dims (l&3)*4.. => flat float4 index l.
// score reduce over 4-lane head group via shfl_xor(1,2).
// ============================================================
__global__ void gather_attn(float* __restrict__ out, int N) {
    int w = (blockIdx.x * blockDim.x + threadIdx.x) >> 5;
    int lane = threadIdx.x & 31;
    if (w >= N) return;

    const float4 q = reinterpret_cast<const float4*>(g_Q)[(size_t)w * 32 + lane];
    int beg = g_row[w], end = g_row[w + 1];

    float ax = 0.f, ay = 0.f, az = 0.f, aw = 0.f, z = 0.f;
    const float4* KV4 = reinterpret_cast<const float4*>(g_KV);

    int i = beg;
    for (; i + 1 < end; i += 2) {   // 2-way pipelined for MLP
        int s0 = g_srcs[i], s1 = g_srcs[i + 1];
        const float4* p0 = KV4 + (size_t)s0 * 64;
        const float4* p1 = KV4 + (size_t)s1 * 64;
        float4 k0 = p0[lane];
        float4 k1 = p1[lane];
        float d0 = k0.x * q.x + k0.y * q.y + k0.z * q.z + k0.w * q.w;
        float d1 = k1.x * q.x + k1.y * q.y + k1.z * q.z + k1.w * q.w;
        d0 += __shfl_xor_sync(0xffffffffu, d0, 1);
        d0 += __shfl_xor_sync(0xffffffffu, d0, 2);
        d1 += __shfl_xor_sync(0xffffffffu, d1, 1);
        d1 += __shfl_xor_sync(0xffffffffu, d1, 2);
        float e0 = __expf(fminf(5.f, fmaxf(-5.f, d0 * 0.25f)));
        float e1 = __expf(fminf(5.f, fmaxf(-5.f, d1 * 0.25f)));
        float4 v0 = p0[32 + lane];
        float4 v1 = p1[32 + lane];
        z  += e0 + e1;
        ax += v0.x * e0 + v1.x * e1;
        ay += v0.y * e0 + v1.y * e1;
        az += v0.z * e0 + v1.z * e1;
        aw += v0.w * e0 + v1.w * e1;
    }
    if (i < end) {
        int s0 = g_srcs[i];
        const float4* p0 = KV4 + (size_t)s0 * 64;
        float4 k0 = p0[lane];
        float d0 = k0.x * q.x + k0.y * q.y + k0.z * q.z + k0.w * q.w;
        d0 += __shfl_xor_sync(0xffffffffu, d0, 1);
        d0 += __shfl_xor_sync(0xffffffffu, d0, 2);
        float e0 = __expf(fminf(5.f, fmaxf(-5.f, d0 * 0.25f)));
        float4 v0 = p0[32 + lane];
        z  += e0;
        ax += v0.x * e0;
        ay += v0.y * e0;
        az += v0.z * e0;
        aw += v0.w * e0;
    }

    float inv = (z > 0.f) ? 1.f / z : 0.f;   // z==0 => acc==0 => out 0 (matches ref)
    reinterpret_cast<float4*>(out)[(size_t)w * 32 + lane] =
        make_float4(ax * inv, ay * inv, az * inv, aw * inv);
}

// ============================================================
extern "C" void kernel_launch(void* const* d_in, const int* in_sizes, int n_in,
                              void* d_out, int out_size) {
    const float* h  = (const float*)d_in[0];
    const int*   src = (const int*)d_in[1];
    const int*   dst = (const int*)d_in[2];
    const float* WQ = (const float*)d_in[3];
    const float* bQ = (const float*)d_in[4];
    const float* WK = (const float*)d_in[5];
    const float* bK = (const float*)d_in[6];
    const float* WV = (const float*)d_in[7];
    const float* bV = (const float*)d_in[8];
    int N = in_sizes[0] / INDIM;
    int E = in_sizes[1];

    const int smem_bytes = (BM * HS + 128 * 128) * (int)sizeof(float);  // ~97 KB
    cudaFuncSetAttribute(qkv_gemm, cudaFuncAttributeMaxDynamicSharedMemorySize, smem_bytes);

    zero_cnt<<<(N + 1 + 255) / 256, 256>>>(N);
    qkv_gemm<<<dim3((N + BM - 1) / BM, 3), 256, smem_bytes>>>(h, WQ, bQ, WK, bK, WV, bV, N);

    hist_k<<<(E + 255) / 256, 256>>>(dst, E);
    int nb = (N + 1023) / 1024;
    scan_partial<<<nb, 1024>>>(N);
    scan_mid<<<1, 1024>>>(nb, N);
    scan_add<<<nb, 1024>>>(N);
    scatter_k<<<(E + 255) / 256, 256>>>(src, dst, E);

    gather_attn<<<(N + 7) / 8, 256>>>((float*)d_out, N);
}

// round 3
// speedup vs baseline: 1.6756x; 1.6756x over previous
#include <cuda_runtime.h>
#include <cuda_bf16.h>
#include <cstdint>

#define NMAX 50000
#define EMAX 800000
#define INDIM 128
#define ODIM 128

// ---- device scratch (no cudaMalloc allowed) ----
__device__ float g_Q[NMAX * ODIM];            // Q[n][128]
__device__ float g_KV[NMAX * 2 * ODIM];       // per node: K[128] | V[128]
__device__ int   g_cnt[NMAX + 1];
__device__ int   g_row[NMAX + 1];
__device__ int   g_cur[NMAX];
__device__ int   g_srcs[EMAX];
__device__ int   g_bsum[64];
__device__ int   g_boff[64];

// ============================================================
// smem helpers
// ============================================================
__device__ __forceinline__ uint32_t smem_u32(const void* p) {
    uint32_t a;
    asm("{ .reg .u64 t; cvta.to.shared.u64 t, %1; cvt.u32.u64 %0, t; }" : "=r"(a) : "l"(p));
    return a;
}
__device__ __forceinline__ void ldm_x4(uint32_t& r0, uint32_t& r1, uint32_t& r2,
                                       uint32_t& r3, uint32_t addr) {
    asm volatile("ldmatrix.sync.aligned.m8n8.x4.shared.b16 {%0,%1,%2,%3}, [%4];"
                 : "=r"(r0), "=r"(r1), "=r"(r2), "=r"(r3) : "r"(addr));
}
__device__ __forceinline__ void mma_bf16(float& c0, float& c1, float& c2, float& c3,
                                         uint32_t a0, uint32_t a1, uint32_t a2, uint32_t a3,
                                         uint32_t b0, uint32_t b1) {
    asm volatile("mma.sync.aligned.m16n8k16.row.col.f32.bf16.bf16.f32 "
                 "{%0,%1,%2,%3}, {%4,%5,%6,%7}, {%8,%9}, {%0,%1,%2,%3};"
                 : "+f"(c0), "+f"(c1), "+f"(c2), "+f"(c3)
                 : "r"(a0), "r"(a1), "r"(a2), "r"(a3), "r"(b0), "r"(b1));
}

// smem tile layout: row stride 136 bf16 = 272 B (odd multiple of 16B -> ldmatrix
// 8-row groups hit distinct 16B bank-groups; conflict-free)
#define TSTRIDE 272
#define A_HI 0
#define A_LO 34816
#define B_HI 69632
#define B_LO 104448
#define SM_TOTAL 139264

// ============================================================
// QKV GEMM via HMMA bf16 hi/lo split (3 terms, fp32 accumulate)
// grid=(NT,3), 256 threads (8 warps, 4x2 warp grid, 32x64 warp tile)
// ============================================================
__global__ void __launch_bounds__(256, 1)
qkv_hmma(const float* __restrict__ h,
         const float* __restrict__ WQ, const float* __restrict__ bQ,
         const float* __restrict__ WK, const float* __restrict__ bK,
         const float* __restrict__ WV, const float* __restrict__ bV,
         int N) {
    extern __shared__ char smem[];
    uint32_t sb = smem_u32(smem);
    int tid = threadIdx.x;
    int t = blockIdx.x, m = blockIdx.y;
    const float* W    = (m == 0) ? WQ : (m == 1) ? WK : WV;
    const float* bias = (m == 0) ? bQ : (m == 1) ? bK : bV;

    // ---- convert h tile [128 nodes x 128] -> A_hi/A_lo (row-major, padded) ----
    {
        int r = tid >> 1, half = tid & 1;
        int node = t * 128 + r;
        const float4* hp = reinterpret_cast<const float4*>(h + (size_t)node * 128);
#pragma unroll
        for (int i = 0; i < 16; i++) {
            int c = half * 64 + i * 4;
            float4 x = make_float4(0.f, 0.f, 0.f, 0.f);
            if (node < N) x = hp[c >> 2];
            float xs[4] = {x.x, x.y, x.z, x.w};
            uint32_t hv[2], lv[2];
#pragma unroll
            for (int p = 0; p < 2; p++) {
                __nv_bfloat16 a = __float2bfloat16(xs[2 * p]);
                __nv_bfloat16 b = __float2bfloat16(xs[2 * p + 1]);
                __nv_bfloat16 la = __float2bfloat16(xs[2 * p] - __bfloat162float(a));
                __nv_bfloat16 lb = __float2bfloat16(xs[2 * p + 1] - __bfloat162float(b));
                hv[p] = (uint32_t)__bfloat16_as_ushort(a) |
                        ((uint32_t)__bfloat16_as_ushort(b) << 16);
                lv[p] = (uint32_t)__bfloat16_as_ushort(la) |
                        ((uint32_t)__bfloat16_as_ushort(lb) << 16);
            }
            *reinterpret_cast<uint2*>(smem + A_HI + r * TSTRIDE + c * 2) =
                make_uint2(hv[0], hv[1]);
            *reinterpret_cast<uint2*>(smem + A_LO + r * TSTRIDE + c * 2) =
                make_uint2(lv[0], lv[1]);
        }
    }

    // ---- convert + transpose W -> Bt_hi/Bt_lo [n][k] (row-major, padded) ----
    {
        int k = tid >> 1, half = tid & 1;
        const float4* wp = reinterpret_cast<const float4*>(W + (size_t)k * 128);
#pragma unroll
        for (int i = 0; i < 16; i++) {
            int c0 = half * 64 + i * 4;
            float4 x = wp[c0 >> 2];
            float xs[4] = {x.x, x.y, x.z, x.w};
#pragma unroll
            for (int j = 0; j < 4; j++) {
                __nv_bfloat16 a = __float2bfloat16(xs[j]);
                __nv_bfloat16 la = __float2bfloat16(xs[j] - __bfloat162float(a));
                int n = c0 + j;
                *reinterpret_cast<__nv_bfloat16*>(smem + B_HI + n * TSTRIDE + k * 2) = a;
                *reinterpret_cast<__nv_bfloat16*>(smem + B_LO + n * TSTRIDE + k * 2) = la;
            }
        }
    }
    __syncthreads();

    // ---- mainloop ----
    int wid = tid >> 5, lane = tid & 31;
    int wm = wid & 3, wn = wid >> 2;          // 4 x 2 warp grid

    // A ldmatrix lane address (relative to tile base): rows 0-15, col-halves
    uint32_t aRel = (uint32_t)((wm * 32 + (lane & 15)) * TSTRIDE + (lane >> 4) * 16);
    // B ldmatrix lane address: lanes0-7 (n0-7,k0-7), 8-15 (n0-7,k8-15),
    //                          16-23 (n8-15,k0-7), 24-31 (n8-15,k8-15)
    uint32_t bRel = (uint32_t)((wn * 64 + (lane & 7) + ((lane >> 4) << 3)) * TSTRIDE +
                               (((lane >> 3) & 1) << 4));

    float acc[2][8][4];
#pragma unroll
    for (int mt = 0; mt < 2; mt++)
#pragma unroll
        for (int nt = 0; nt < 8; nt++)
#pragma unroll
            for (int q = 0; q < 4; q++) acc[mt][nt][q] = 0.f;

#pragma unroll
    for (int term = 0; term < 3; term++) {
        uint32_t aBase = sb + ((term == 1) ? A_LO : A_HI) + aRel;
        uint32_t bBase = sb + ((term == 2) ? B_LO : B_HI) + bRel;
#pragma unroll
        for (int k16 = 0; k16 < 8; k16++) {
            uint32_t af[2][4];
            ldm_x4(af[0][0], af[0][1], af[0][2], af[0][3], aBase + k16 * 32);
            ldm_x4(af[1][0], af[1][1], af[1][2], af[1][3],
                   aBase + 16 * TSTRIDE + k16 * 32);
            uint32_t bf[4][4];
#pragma unroll
            for (int nb = 0; nb < 4; nb++)
                ldm_x4(bf[nb][0], bf[nb][1], bf[nb][2], bf[nb][3],
                       bBase + nb * 16 * TSTRIDE + k16 * 32);
#pragma unroll
            for (int mt = 0; mt < 2; mt++)
#pragma unroll
                for (int nb = 0; nb < 4; nb++) {
                    mma_bf16(acc[mt][nb * 2][0], acc[mt][nb * 2][1],
                             acc[mt][nb * 2][2], acc[mt][nb * 2][3],
                             af[mt][0], af[mt][1], af[mt][2], af[mt][3],
                             bf[nb][0], bf[nb][1]);
                    mma_bf16(acc[mt][nb * 2 + 1][0], acc[mt][nb * 2 + 1][1],
                             acc[mt][nb * 2 + 1][2], acc[mt][nb * 2 + 1][3],
                             af[mt][0], af[mt][1], af[mt][2], af[mt][3],
                             bf[nb][2], bf[nb][3]);
                }
        }
    }

    // ---- epilogue: bias + direct stores ----
#pragma unroll
    for (int nt = 0; nt < 8; nt++) {
        int col = wn * 64 + nt * 8 + (lane & 3) * 2;
        float b0 = bias[col], b1 = bias[col + 1];
#pragma unroll
        for (int mt = 0; mt < 2; mt++) {
            int row = t * 128 + wm * 32 + mt * 16 + (lane >> 2);
            if (row < N) {
                float* o = (m == 0) ? (g_Q + (size_t)row * 128 + col)
                                    : (g_KV + (size_t)row * 256 + (m == 2 ? 128 : 0) + col);
                *reinterpret_cast<float2*>(o) =
                    make_float2(acc[mt][nt][0] + b0, acc[mt][nt][1] + b1);
            }
            int row2 = row + 8;
            if (row2 < N) {
                float* o = (m == 0) ? (g_Q + (size_t)row2 * 128 + col)
                                    : (g_KV + (size_t)row2 * 256 + (m == 2 ? 128 : 0) + col);
                *reinterpret_cast<float2*>(o) =
                    make_float2(acc[mt][nt][2] + b0, acc[mt][nt][3] + b1);
            }
        }
    }
}

// ============================================================
// CSR construction
// ============================================================
__global__ void zero_cnt(int N) {
    int i = blockIdx.x * 256 + threadIdx.x;
    if (i <= N) g_cnt[i] = 0;
}

__global__ void hist_k(const int* __restrict__ dst, int E) {
    int e = blockIdx.x * 256 + threadIdx.x;
    if (e < E) atomicAdd(&g_cnt[dst[e]], 1);
}

__global__ void scan_partial(int N) {
    __shared__ int s[1024];
    int tid = threadIdx.x;
    int idx = blockIdx.x * 1024 + tid;
    int x = (idx < N) ? g_cnt[idx] : 0;
    s[tid] = x;
    __syncthreads();
    for (int off = 1; off < 1024; off <<= 1) {
        int t = (tid >= off) ? s[tid - off] : 0;
        __syncthreads();
        if (tid >= off) s[tid] += t;
        __syncthreads();
    }
    if (idx < N) g_row[idx] = s[tid] - x;
    if (tid == 1023) g_bsum[blockIdx.x] = s[1023];
}

__global__ void scan_mid(int nb, int N) {
    __shared__ int s[1024];
    int tid = threadIdx.x;
    int x = (tid < nb) ? g_bsum[tid] : 0;
    s[tid] = x;
    __syncthreads();
    for (int off = 1; off < 1024; off <<= 1) {
        int t = (tid >= off) ? s[tid - off] : 0;
        __syncthreads();
        if (tid >= off) s[tid] += t;
        __syncthreads();
    }
    if (tid < nb) g_boff[tid] = s[tid] - x;
    if (tid == nb - 1) g_row[N] = s[tid];
}

__global__ void scan_add(int N) {
    int idx = blockIdx.x * 1024 + threadIdx.x;
    if (idx < N) {
        int v = g_row[idx] + g_boff[blockIdx.x];
        g_row[idx] = v;
        g_cur[idx] = v;
    }
}

__global__ void scatter_k(const int* __restrict__ src, const int* __restrict__ dst, int E) {
    int e = blockIdx.x * 256 + threadIdx.x;
    if (e < E) {
        int pos = atomicAdd(&g_cur[dst[e]], 1);
        g_srcs[pos] = src[e];
    }
}

// ============================================================
// Gather attention: one warp per dst node
// ============================================================
__global__ void gather_attn(float* __restrict__ out, int N) {
    int w = (blockIdx.x * blockDim.x + threadIdx.x) >> 5;
    int lane = threadIdx.x & 31;
    if (w >= N) return;

    const float4 q = reinterpret_cast<const float4*>(g_Q)[(size_t)w * 32 + lane];
    int beg = g_row[w], end = g_row[w + 1];

    float ax = 0.f, ay = 0.f, az = 0.f, aw = 0.f, z = 0.f;
    const float4* KV4 = reinterpret_cast<const float4*>(g_KV);

    int i = beg;
    for (; i + 1 < end; i += 2) {
        int s0 = g_srcs[i], s1 = g_srcs[i + 1];
        const float4* p0 = KV4 + (size_t)s0 * 64;
        const float4* p1 = KV4 + (size_t)s1 * 64;
        float4 k0 = p0[lane];
        float4 k1 = p1[lane];
        float d0 = k0.x * q.x + k0.y * q.y + k0.z * q.z + k0.w * q.w;
        float d1 = k1.x * q.x + k1.y * q.y + k1.z * q.z + k1.w * q.w;
        d0 += __shfl_xor_sync(0xffffffffu, d0, 1);
        d0 += __shfl_xor_sync(0xffffffffu, d0, 2);
        d1 += __shfl_xor_sync(0xffffffffu, d1, 1);
        d1 += __shfl_xor_sync(0xffffffffu, d1, 2);
        float e0 = __expf(fminf(5.f, fmaxf(-5.f, d0 * 0.25f)));
        float e1 = __expf(fminf(5.f, fmaxf(-5.f, d1 * 0.25f)));
        float4 v0 = p0[32 + lane];
        float4 v1 = p1[32 + lane];
        z  += e0 + e1;
        ax += v0.x * e0 + v1.x * e1;
        ay += v0.y * e0 + v1.y * e1;
        az += v0.z * e0 + v1.z * e1;
        aw += v0.w * e0 + v1.w * e1;
    }
    if (i < end) {
        int s0 = g_srcs[i];
        const float4* p0 = KV4 + (size_t)s0 * 64;
        float4 k0 = p0[lane];
        float d0 = k0.x * q.x + k0.y * q.y + k0.z * q.z + k0.w * q.w;
        d0 += __shfl_xor_sync(0xffffffffu, d0, 1);
        d0 += __shfl_xor_sync(0xffffffffu, d0, 2);
        float e0 = __expf(fminf(5.f, fmaxf(-5.f, d0 * 0.25f)));
        float4 v0 = p0[32 + lane];
        z  += e0;
        ax += v0.x * e0;
        ay += v0.y * e0;
        az += v0.z * e0;
        aw += v0.w * e0;
    }

    float inv = (z > 0.f) ? 1.f / z : 0.f;
    reinterpret_cast<float4*>(out)[(size_t)w * 32 + lane] =
        make_float4(ax * inv, ay * inv, az * inv, aw * inv);
}

// ============================================================
extern "C" void kernel_launch(void* const* d_in, const int* in_sizes, int n_in,
                              void* d_out, int out_size) {
    const float* h  = (const float*)d_in[0];
    const int*   src = (const int*)d_in[1];
    const int*   dst = (const int*)d_in[2];
    const float* WQ = (const float*)d_in[3];
    const float* bQ = (const float*)d_in[4];
    const float* WK = (const float*)d_in[5];
    const float* bK = (const float*)d_in[6];
    const float* WV = (const float*)d_in[7];
    const float* bV = (const float*)d_in[8];
    int N = in_sizes[0] / INDIM;
    int E = in_sizes[1];
    int NT = (N + 127) / 128;

    cudaFuncSetAttribute(qkv_hmma, cudaFuncAttributeMaxDynamicSharedMemorySize, SM_TOTAL);

    zero_cnt<<<(N + 1 + 255) / 256, 256>>>(N);
    qkv_hmma<<<dim3(NT, 3), 256, SM_TOTAL>>>(h, WQ, bQ, WK, bK, WV, bV, N);

    hist_k<<<(E + 255) / 256, 256>>>(dst, E);
    int nb = (N + 1023) / 1024;
    scan_partial<<<nb, 1024>>>(N);
    scan_mid<<<1, 1024>>>(nb, N);
    scan_add<<<nb, 1024>>>(N);
    scatter_k<<<(E + 255) / 256, 256>>>(src, dst, E);

    gather_attn<<<(N + 7) / 8, 256>>>((float*)d_out, N);
}

// round 4
// speedup vs baseline: 1.9815x; 1.1826x over previous
#include <cuda_runtime.h>
#include <cuda_bf16.h>
#include <cuda_fp16.h>
#include <cstdint>

#define NMAX 50000
#define EMAX 800000
#define INDIM 128
#define ODIM 128

// ---- device scratch (no cudaMalloc allowed) ----
__device__ float  g_Q[NMAX * ODIM];           // Q[n][128] fp32
__device__ __half g_KVh[NMAX * 2 * ODIM];     // per node: K[128] | V[128] fp16 (512B)
__device__ unsigned char g_WThi[3][34816];    // W^T bf16 hi, padded stride 272B
__device__ unsigned char g_WTlo[3][34816];    // W^T bf16 lo
__device__ int   g_cnt[NMAX + 1];
__device__ int   g_row[NMAX + 1];
__device__ int   g_cur[NMAX];
__device__ int   g_srcs[EMAX];
__device__ int   g_bsum[64];
__device__ int   g_boff[64];

// ============================================================
// helpers
// ============================================================
__device__ __forceinline__ uint32_t smem_u32(const void* p) {
    uint32_t a;
    asm("{ .reg .u64 t; cvta.to.shared.u64 t, %1; cvt.u32.u64 %0, t; }" : "=r"(a) : "l"(p));
    return a;
}
__device__ __forceinline__ void ldm_x4(uint32_t& r0, uint32_t& r1, uint32_t& r2,
                                       uint32_t& r3, uint32_t addr) {
    asm volatile("ldmatrix.sync.aligned.m8n8.x4.shared.b16 {%0,%1,%2,%3}, [%4];"
                 : "=r"(r0), "=r"(r1), "=r"(r2), "=r"(r3) : "r"(addr));
}
__device__ __forceinline__ void mma_bf16(float& c0, float& c1, float& c2, float& c3,
                                         uint32_t a0, uint32_t a1, uint32_t a2, uint32_t a3,
                                         uint32_t b0, uint32_t b1) {
    asm volatile("mma.sync.aligned.m16n8k16.row.col.f32.bf16.bf16.f32 "
                 "{%0,%1,%2,%3}, {%4,%5,%6,%7}, {%8,%9}, {%0,%1,%2,%3};"
                 : "+f"(c0), "+f"(c1), "+f"(c2), "+f"(c3)
                 : "r"(a0), "r"(a1), "r"(a2), "r"(a3), "r"(b0), "r"(b1));
}

// smem tile layout: row stride 136 bf16 = 272 B
#define TSTRIDE 272
#define A_HI 0
#define A_LO 34816
#define B_HI 69632
#define B_LO 104448
#define SM_TOTAL 139264

// ============================================================
// W^T conversion to bf16 hi/lo (once): 3 CTAs, smem transpose
// ============================================================
__global__ void conv_W(const float* __restrict__ WQ, const float* __restrict__ WK,
                       const float* __restrict__ WV) {
    extern __shared__ float ws[];               // 128 x 132 floats
    int m = blockIdx.x, tid = threadIdx.x;
    const float* W = (m == 0) ? WQ : (m == 1) ? WK : WV;

    for (int i = tid; i < 4096; i += 256) {     // 128 rows x 32 float4, coalesced
        int r = i >> 5, c4 = i & 31;
        float4 v = reinterpret_cast<const float4*>(W)[r * 32 + c4];
        *reinterpret_cast<float4*>(ws + r * 132 + c4 * 4) = v;
    }
    __syncthreads();

    int n = tid >> 1, kh = tid & 1;             // thread: one n row, 64 k's
#pragma unroll
    for (int i = 0; i < 8; i++) {
        int k0 = kh * 64 + i * 8;
        uint32_t hw[4], lw[4];
#pragma unroll
        for (int p = 0; p < 4; p++) {
            float xa = ws[(k0 + 2 * p) * 132 + n];
            float xb = ws[(k0 + 2 * p + 1) * 132 + n];
            __nv_bfloat16 a = __float2bfloat16(xa);
            __nv_bfloat16 b = __float2bfloat16(xb);
            __nv_bfloat16 la = __float2bfloat16(xa - __bfloat162float(a));
            __nv_bfloat16 lb = __float2bfloat16(xb - __bfloat162float(b));
            hw[p] = (uint32_t)__bfloat16_as_ushort(a) | ((uint32_t)__bfloat16_as_ushort(b) << 16);
            lw[p] = (uint32_t)__bfloat16_as_ushort(la) | ((uint32_t)__bfloat16_as_ushort(lb) << 16);
        }
        *reinterpret_cast<uint4*>(g_WThi[m] + n * TSTRIDE + k0 * 2) =
            make_uint4(hw[0], hw[1], hw[2], hw[3]);
        *reinterpret_cast<uint4*>(g_WTlo[m] + n * TSTRIDE + k0 * 2) =
            make_uint4(lw[0], lw[1], lw[2], lw[3]);
    }
}

// ============================================================
// QKV GEMM: one CTA per 128-node tile; loops m = Q,K,V.
// A (h tile) converted to bf16 hi/lo ONCE; B copied from g_WT.
// Q stored fp32; K/V stored fp16 to g_KVh.
// ============================================================
__global__ void __launch_bounds__(256, 1)
qkv_hmma(const float* __restrict__ h,
         const float* __restrict__ bQ, const float* __restrict__ bK,
         const float* __restrict__ bV, int N) {
    extern __shared__ char smem[];
    uint32_t sb = smem_u32(smem);
    int tid = threadIdx.x;
    int t = blockIdx.x;

    // ---- convert h tile [128 x 128] -> A_hi/A_lo (once) ----
    {
        int r = tid >> 1, half = tid & 1;
        int node = t * 128 + r;
        const float4* hp = reinterpret_cast<const float4*>(h + (size_t)node * 128);
#pragma unroll
        for (int i = 0; i < 16; i++) {
            int c = half * 64 + i * 4;
            float4 x = make_float4(0.f, 0.f, 0.f, 0.f);
            if (node < N) x = hp[c >> 2];
            float xs[4] = {x.x, x.y, x.z, x.w};
            uint32_t hv[2], lv[2];
#pragma unroll
            for (int p = 0; p < 2; p++) {
                __nv_bfloat16 a = __float2bfloat16(xs[2 * p]);
                __nv_bfloat16 b = __float2bfloat16(xs[2 * p + 1]);
                __nv_bfloat16 la = __float2bfloat16(xs[2 * p] - __bfloat162float(a));
                __nv_bfloat16 lb = __float2bfloat16(xs[2 * p + 1] - __bfloat162float(b));
                hv[p] = (uint32_t)__bfloat16_as_ushort(a) | ((uint32_t)__bfloat16_as_ushort(b) << 16);
                lv[p] = (uint32_t)__bfloat16_as_ushort(la) | ((uint32_t)__bfloat16_as_ushort(lb) << 16);
            }
            *reinterpret_cast<uint2*>(smem + A_HI + r * TSTRIDE + c * 2) = make_uint2(hv[0], hv[1]);
            *reinterpret_cast<uint2*>(smem + A_LO + r * TSTRIDE + c * 2) = make_uint2(lv[0], lv[1]);
        }
    }

    int wid = tid >> 5, lane = tid & 31;
    int wm = wid & 3, wn = wid >> 2;            // 4 x 2 warp grid, 32x64 warp tile
    uint32_t aRel = (uint32_t)((wm * 32 + (lane & 15)) * TSTRIDE + (lane >> 4) * 16);
    uint32_t bRel = (uint32_t)((wn * 64 + (lane & 7) + ((lane >> 4) << 3)) * TSTRIDE +
                               (((lane >> 3) & 1) << 4));

    for (int m = 0; m < 3; m++) {
        // ---- copy W^T bf16 tiles into smem (pure uint4 copy) ----
        {
            const uint4* sH = reinterpret_cast<const uint4*>(g_WThi[m]);
            const uint4* sL = reinterpret_cast<const uint4*>(g_WTlo[m]);
            uint4* dH = reinterpret_cast<uint4*>(smem + B_HI);
            uint4* dL = reinterpret_cast<uint4*>(smem + B_LO);
            for (int i = tid; i < 2176; i += 256) {
                dH[i] = sH[i];
                dL[i] = sL[i];
            }
        }
        __syncthreads();   // A (first iter) + B ready; prior mainloop done

        float acc[2][8][4];
#pragma unroll
        for (int mt = 0; mt < 2; mt++)
#pragma unroll
            for (int nt = 0; nt < 8; nt++)
#pragma unroll
                for (int q = 0; q < 4; q++) acc[mt][nt][q] = 0.f;

#pragma unroll
        for (int term = 0; term < 3; term++) {
            uint32_t aBase = sb + ((term == 1) ? A_LO : A_HI) + aRel;
            uint32_t bBase = sb + ((term == 2) ? B_LO : B_HI) + bRel;
#pragma unroll
            for (int k16 = 0; k16 < 8; k16++) {
                uint32_t af[2][4];
                ldm_x4(af[0][0], af[0][1], af[0][2], af[0][3], aBase + k16 * 32);
                ldm_x4(af[1][0], af[1][1], af[1][2], af[1][3], aBase + 16 * TSTRIDE + k16 * 32);
                uint32_t bf[4][4];
#pragma unroll
                for (int nb = 0; nb < 4; nb++)
                    ldm_x4(bf[nb][0], bf[nb][1], bf[nb][2], bf[nb][3],
                           bBase + nb * 16 * TSTRIDE + k16 * 32);
#pragma unroll
                for (int mt = 0; mt < 2; mt++)
#pragma unroll
                    for (int nb = 0; nb < 4; nb++) {
                        mma_bf16(acc[mt][nb * 2][0], acc[mt][nb * 2][1],
                                 acc[mt][nb * 2][2], acc[mt][nb * 2][3],
                                 af[mt][0], af[mt][1], af[mt][2], af[mt][3],
                                 bf[nb][0], bf[nb][1]);
                        mma_bf16(acc[mt][nb * 2 + 1][0], acc[mt][nb * 2 + 1][1],
                                 acc[mt][nb * 2 + 1][2], acc[mt][nb * 2 + 1][3],
                                 af[mt][0], af[mt][1], af[mt][2], af[mt][3],
                                 bf[nb][2], bf[nb][3]);
                    }
            }
        }

        // ---- epilogue ----
        const float* bias = (m == 0) ? bQ : (m == 1) ? bK : bV;
#pragma unroll
        for (int nt = 0; nt < 8; nt++) {
            int col = wn * 64 + nt * 8 + (lane & 3) * 2;
            float b0 = bias[col], b1 = bias[col + 1];
#pragma unroll
            for (int mt = 0; mt < 2; mt++) {
                int row = t * 128 + wm * 32 + mt * 16 + (lane >> 2);
#pragma unroll
                for (int half = 0; half < 2; half++) {
                    int rr = row + half * 8;
                    if (rr >= N) continue;
                    float v0 = acc[mt][nt][2 * half] + b0;
                    float v1 = acc[mt][nt][2 * half + 1] + b1;
                    if (m == 0) {
                        *reinterpret_cast<float2*>(g_Q + (size_t)rr * 128 + col) =
                            make_float2(v0, v1);
                    } else {
                        __half2* o = reinterpret_cast<__half2*>(
                            g_KVh + (size_t)rr * 256 + (m == 2 ? 128 : 0) + col);
                        *o = __floats2half2_rn(v0, v1);
                    }
                }
            }
        }
        __syncthreads();   // all warps done reading B before next m overwrites
    }
}

// ============================================================
// CSR construction
// ============================================================
__global__ void zero_cnt(int N) {
    int i = blockIdx.x * 256 + threadIdx.x;
    if (i <= N) g_cnt[i] = 0;
}

__global__ void hist_k(const int* __restrict__ dst, int E) {
    int e = blockIdx.x * 256 + threadIdx.x;
    if (e < E) atomicAdd(&g_cnt[dst[e]], 1);
}

__device__ __forceinline__ int warp_incl_scan(int v, int lane) {
#pragma unroll
    for (int off = 1; off < 32; off <<= 1) {
        int t = __shfl_up_sync(0xffffffffu, v, off);
        if (lane >= off) v += t;
    }
    return v;
}

__global__ void scan_partial(int N) {
    __shared__ int wsum[32];
    int tid = threadIdx.x, lane = tid & 31, wid = tid >> 5;
    int idx = blockIdx.x * 1024 + tid;
    int x = (idx < N) ? g_cnt[idx] : 0;
    int v = warp_incl_scan(x, lane);
    if (lane == 31) wsum[wid] = v;
    __syncthreads();
    if (wid == 0) wsum[lane] = warp_incl_scan(wsum[lane], lane);
    __syncthreads();
    int incl = v + (wid > 0 ? wsum[wid - 1] : 0);
    if (idx < N) g_row[idx] = incl - x;
    if (tid == 1023) g_bsum[blockIdx.x] = incl;
}

__global__ void scan_mid(int nb, int N) {
    __shared__ int wsum[32];
    int tid = threadIdx.x, lane = tid & 31, wid = tid >> 5;
    int x = (tid < nb) ? g_bsum[tid] : 0;
    int v = warp_incl_scan(x, lane);
    if (lane == 31) wsum[wid] = v;
    __syncthreads();
    if (wid == 0) wsum[lane] = warp_incl_scan(wsum[lane], lane);
    __syncthreads();
    int incl = v + (wid > 0 ? wsum[wid - 1] : 0);
    if (tid < nb) g_boff[tid] = incl - x;
    if (tid == nb - 1) g_row[N] = incl;
}

__global__ void scan_add(int N) {
    int idx = blockIdx.x * 1024 + threadIdx.x;
    if (idx < N) {
        int v = g_row[idx] + g_boff[blockIdx.x];
        g_row[idx] = v;
        g_cur[idx] = v;
    }
}

__global__ void scatter_k(const int* __restrict__ src, const int* __restrict__ dst, int E) {
    int e = blockIdx.x * 256 + threadIdx.x;
    if (e < E) {
        int pos = atomicAdd(&g_cur[dst[e]], 1);
        g_srcs[pos] = src[e];
    }
}

// ============================================================
// Gather attention: one warp per dst node, fp16 KV
// lane l: head l>>2, flat dims 4l..4l+3. uint2 (8B) per lane per K/V.
// ============================================================
__global__ void gather_attn(float* __restrict__ out, int N) {
    int w = (blockIdx.x * blockDim.x + threadIdx.x) >> 5;
    int lane = threadIdx.x & 31;
    if (w >= N) return;

    const float4 q = reinterpret_cast<const float4*>(g_Q)[(size_t)w * 32 + lane];
    int beg = g_row[w], end = g_row[w + 1];

    float ax = 0.f, ay = 0.f, az = 0.f, aw = 0.f, z = 0.f;
    const uint2* KV = reinterpret_cast<const uint2*>(g_KVh);

    int i = beg;
    for (; i + 1 < end; i += 2) {
        int s0 = g_srcs[i], s1 = g_srcs[i + 1];
        const uint2* p0 = KV + (size_t)s0 * 64;
        const uint2* p1 = KV + (size_t)s1 * 64;
        uint2 kr0 = p0[lane];
        uint2 kr1 = p1[lane];
        float2 k0a = __half22float2(*reinterpret_cast<__half2*>(&kr0.x));
        float2 k0b = __half22float2(*reinterpret_cast<__half2*>(&kr0.y));
        float2 k1a = __half22float2(*reinterpret_cast<__half2*>(&kr1.x));
        float2 k1b = __half22float2(*reinterpret_cast<__half2*>(&kr1.y));
        float d0 = k0a.x * q.x + k0a.y * q.y + k0b.x * q.z + k0b.y * q.w;
        float d1 = k1a.x * q.x + k1a.y * q.y + k1b.x * q.z + k1b.y * q.w;
        d0 += __shfl_xor_sync(0xffffffffu, d0, 1);
        d0 += __shfl_xor_sync(0xffffffffu, d0, 2);
        d1 += __shfl_xor_sync(0xffffffffu, d1, 1);
        d1 += __shfl_xor_sync(0xffffffffu, d1, 2);
        float e0 = __expf(fminf(5.f, fmaxf(-5.f, d0 * 0.25f)));
        float e1 = __expf(fminf(5.f, fmaxf(-5.f, d1 * 0.25f)));
        uint2 vr0 = p0[32 + lane];
        uint2 vr1 = p1[32 + lane];
        float2 v0a = __half22float2(*reinterpret_cast<__half2*>(&vr0.x));
        float2 v0b = __half22float2(*reinterpret_cast<__half2*>(&vr0.y));
        float2 v1a = __half22float2(*reinterpret_cast<__half2*>(&vr1.x));
        float2 v1b = __half22float2(*reinterpret_cast<__half2*>(&vr1.y));
        z  += e0 + e1;
        ax += v0a.x * e0 + v1a.x * e1;
        ay += v0a.y * e0 + v1a.y * e1;
        az += v0b.x * e0 + v1b.x * e1;
        aw += v0b.y * e0 + v1b.y * e1;
    }
    if (i < end) {
        int s0 = g_srcs[i];
        const uint2* p0 = KV + (size_t)s0 * 64;
        uint2 kr0 = p0[lane];
        float2 k0a = __half22float2(*reinterpret_cast<__half2*>(&kr0.x));
        float2 k0b = __half22float2(*reinterpret_cast<__half2*>(&kr0.y));
        float d0 = k0a.x * q.x + k0a.y * q.y + k0b.x * q.z + k0b.y * q.w;
        d0 += __shfl_xor_sync(0xffffffffu, d0, 1);
        d0 += __shfl_xor_sync(0xffffffffu, d0, 2);
        float e0 = __expf(fminf(5.f, fmaxf(-5.f, d0 * 0.25f)));
        uint2 vr0 = p0[32 + lane];
        float2 v0a = __half22float2(*reinterpret_cast<__half2*>(&vr0.x));
        float2 v0b = __half22float2(*reinterpret_cast<__half2*>(&vr0.y));
        z  += e0;
        ax += v0a.x * e0;
        ay += v0a.y * e0;
        az += v0b.x * e0;
        aw += v0b.y * e0;
    }

    float inv = (z > 0.f) ? 1.f / z : 0.f;
    reinterpret_cast<float4*>(out)[(size_t)w * 32 + lane] =
        make_float4(ax * inv, ay * inv, az * inv, aw * inv);
}

// ============================================================
extern "C" void kernel_launch(void* const* d_in, const int* in_sizes, int n_in,
                              void* d_out, int out_size) {
    const float* h  = (const float*)d_in[0];
    const int*   src = (const int*)d_in[1];
    const int*   dst = (const int*)d_in[2];
    const float* WQ = (const float*)d_in[3];
    const float* bQ = (const float*)d_in[4];
    const float* WK = (const float*)d_in[5];
    const float* bK = (const float*)d_in[6];
    const float* WV = (const float*)d_in[7];
    const float* bV = (const float*)d_in[8];
    int N = in_sizes[0] / INDIM;
    int E = in_sizes[1];
    int NT = (N + 127) / 128;

    cudaFuncSetAttribute(qkv_hmma, cudaFuncAttributeMaxDynamicSharedMemorySize, SM_TOTAL);
    cudaFuncSetAttribute(conv_W, cudaFuncAttributeMaxDynamicSharedMemorySize, 128 * 132 * 4);

    zero_cnt<<<(N + 1 + 255) / 256, 256>>>(N);
    conv_W<<<3, 256, 128 * 132 * 4>>>(WQ, WK, WV);
    qkv_hmma<<<NT, 256, SM_TOTAL>>>(h, bQ, bK, bV, N);

    hist_k<<<(E + 255) / 256, 256>>>(dst, E);
    int nb = (N + 1023) / 1024;
    scan_partial<<<nb, 1024>>>(N);
    scan_mid<<<1, 1024>>>(nb, N);
    scan_add<<<nb, 1024>>>(N);
    scatter_k<<<(E + 255) / 256, 256>>>(src, dst, E);

    gather_attn<<<(N + 7) / 8, 256>>>((float*)d_out, N);
}

// round 5
// speedup vs baseline: 2.0895x; 1.0545x over previous
#include <cuda_runtime.h>
#include <cuda_bf16.h>
#include <cuda_fp16.h>
#include <cstdint>

#define NMAX 50000
#define EMAX 800000
#define INDIM 128
#define ODIM 128

// ---- device scratch (no cudaMalloc allowed) ----
__device__ float  g_Q[NMAX * ODIM];           // Q[n][128] fp32
__device__ __half g_KVh[NMAX * 2 * ODIM];     // per node: K[128] | V[128] fp16
__device__ unsigned char g_WThi[3][34816];    // W^T bf16 hi, padded stride 272B
__device__ unsigned char g_WTlo[3][34816];    // W^T bf16 lo
__device__ int   g_cnt[NMAX + 1];
__device__ int   g_row[NMAX + 1];
__device__ int   g_cur[NMAX];
__device__ int   g_srcs[EMAX];
__device__ int   g_bsum[64];
__device__ int   g_boff[64];

// ============================================================
// helpers
// ============================================================
__device__ __forceinline__ uint32_t smem_u32(const void* p) {
    uint32_t a;
    asm("{ .reg .u64 t; cvta.to.shared.u64 t, %1; cvt.u32.u64 %0, t; }" : "=r"(a) : "l"(p));
    return a;
}
__device__ __forceinline__ void ldm_x4(uint32_t& r0, uint32_t& r1, uint32_t& r2,
                                       uint32_t& r3, uint32_t addr) {
    asm volatile("ldmatrix.sync.aligned.m8n8.x4.shared.b16 {%0,%1,%2,%3}, [%4];"
                 : "=r"(r0), "=r"(r1), "=r"(r2), "=r"(r3) : "r"(addr));
}
__device__ __forceinline__ void mma_bf16(float& c0, float& c1, float& c2, float& c3,
                                         uint32_t a0, uint32_t a1, uint32_t a2, uint32_t a3,
                                         uint32_t b0, uint32_t b1) {
    asm volatile("mma.sync.aligned.m16n8k16.row.col.f32.bf16.bf16.f32 "
                 "{%0,%1,%2,%3}, {%4,%5,%6,%7}, {%8,%9}, {%0,%1,%2,%3};"
                 : "+f"(c0), "+f"(c1), "+f"(c2), "+f"(c3)
                 : "r"(a0), "r"(a1), "r"(a2), "r"(a3), "r"(b0), "r"(b1));
}

// smem tile layout: row stride 136 bf16 = 272 B
#define TSTRIDE 272
#define A_HI 0
#define A_LO 34816
#define B_HI 69632
#define B_LO 104448
#define SM_TOTAL 139264

// ============================================================
// W^T conversion to bf16 hi/lo (once): 3 CTAs, smem transpose
// ============================================================
__global__ void conv_W(const float* __restrict__ WQ, const float* __restrict__ WK,
                       const float* __restrict__ WV) {
    extern __shared__ float ws[];               // 128 x 132 floats
    int m = blockIdx.x, tid = threadIdx.x;
    const float* W = (m == 0) ? WQ : (m == 1) ? WK : WV;

    for (int i = tid; i < 4096; i += 256) {
        int r = i >> 5, c4 = i & 31;
        float4 v = reinterpret_cast<const float4*>(W)[r * 32 + c4];
        *reinterpret_cast<float4*>(ws + r * 132 + c4 * 4) = v;
    }
    __syncthreads();

    int n = tid >> 1, kh = tid & 1;
#pragma unroll
    for (int i = 0; i < 8; i++) {
        int k0 = kh * 64 + i * 8;
        uint32_t hw[4], lw[4];
#pragma unroll
        for (int p = 0; p < 4; p++) {
            float xa = ws[(k0 + 2 * p) * 132 + n];
            float xb = ws[(k0 + 2 * p + 1) * 132 + n];
            __nv_bfloat16 a = __float2bfloat16(xa);
            __nv_bfloat16 b = __float2bfloat16(xb);
            __nv_bfloat16 la = __float2bfloat16(xa - __bfloat162float(a));
            __nv_bfloat16 lb = __float2bfloat16(xb - __bfloat162float(b));
            hw[p] = (uint32_t)__bfloat16_as_ushort(a) | ((uint32_t)__bfloat16_as_ushort(b) << 16);
            lw[p] = (uint32_t)__bfloat16_as_ushort(la) | ((uint32_t)__bfloat16_as_ushort(lb) << 16);
        }
        *reinterpret_cast<uint4*>(g_WThi[m] + n * TSTRIDE + k0 * 2) =
            make_uint4(hw[0], hw[1], hw[2], hw[3]);
        *reinterpret_cast<uint4*>(g_WTlo[m] + n * TSTRIDE + k0 * 2) =
            make_uint4(lw[0], lw[1], lw[2], lw[3]);
    }
}

// ============================================================
// QKV GEMM: one CTA per 128-node tile; loops m = Q,K,V.
// A split: hi = PRMT-truncated top16, lo = rn-bf16 of residual.
// ============================================================
__global__ void __launch_bounds__(256, 1)
qkv_hmma(const float* __restrict__ h,
         const float* __restrict__ bQ, const float* __restrict__ bK,
         const float* __restrict__ bV, int N) {
    extern __shared__ char smem[];
    uint32_t sb = smem_u32(smem);
    int tid = threadIdx.x;
    int t = blockIdx.x;

    // ---- convert h tile [128 x 128] -> A_hi/A_lo (once) ----
    {
        int r = tid >> 1, half = tid & 1;
        int node = t * 128 + r;
        const float4* hp = reinterpret_cast<const float4*>(h + (size_t)node * 128);
#pragma unroll
        for (int i = 0; i < 16; i++) {
            int c = half * 64 + i * 4;
            float4 x = make_float4(0.f, 0.f, 0.f, 0.f);
            if (node < N) x = hp[c >> 2];
            uint32_t ua = __float_as_uint(x.x), ub = __float_as_uint(x.y);
            uint32_t uc = __float_as_uint(x.z), ud = __float_as_uint(x.w);
            uint32_t h0 = __byte_perm(ua, ub, 0x7632);   // [a.hi16 | b.hi16]
            uint32_t h1 = __byte_perm(uc, ud, 0x7632);
            float la = x.x - __uint_as_float(ua & 0xFFFF0000u);
            float lb = x.y - __uint_as_float(ub & 0xFFFF0000u);
            float lc = x.z - __uint_as_float(uc & 0xFFFF0000u);
            float ld = x.w - __uint_as_float(ud & 0xFFFF0000u);
            uint32_t l0, l1;
            asm("cvt.rn.bf16x2.f32 %0, %1, %2;" : "=r"(l0) : "f"(lb), "f"(la));
            asm("cvt.rn.bf16x2.f32 %0, %1, %2;" : "=r"(l1) : "f"(ld), "f"(lc));
            *reinterpret_cast<uint2*>(smem + A_HI + r * TSTRIDE + c * 2) = make_uint2(h0, h1);
            *reinterpret_cast<uint2*>(smem + A_LO + r * TSTRIDE + c * 2) = make_uint2(l0, l1);
        }
    }

    int wid = tid >> 5, lane = tid & 31;
    int wm = wid & 3, wn = wid >> 2;            // 4 x 2 warp grid, 32x64 warp tile
    uint32_t aRel = (uint32_t)((wm * 32 + (lane & 15)) * TSTRIDE + (lane >> 4) * 16);
    uint32_t bRel = (uint32_t)((wn * 64 + (lane & 7) + ((lane >> 4) << 3)) * TSTRIDE +
                               (((lane >> 3) & 1) << 4));

    for (int m = 0; m < 3; m++) {
        // ---- copy W^T bf16 tiles into smem ----
        {
            const uint4* sH = reinterpret_cast<const uint4*>(g_WThi[m]);
            const uint4* sL = reinterpret_cast<const uint4*>(g_WTlo[m]);
            uint4* dH = reinterpret_cast<uint4*>(smem + B_HI);
            uint4* dL = reinterpret_cast<uint4*>(smem + B_LO);
            for (int i = tid; i < 2176; i += 256) {
                dH[i] = sH[i];
                dL[i] = sL[i];
            }
        }
        __syncthreads();

        float acc[2][8][4];
#pragma unroll
        for (int mt = 0; mt < 2; mt++)
#pragma unroll
            for (int nt = 0; nt < 8; nt++)
#pragma unroll
                for (int q = 0; q < 4; q++) acc[mt][nt][q] = 0.f;

#pragma unroll
        for (int term = 0; term < 3; term++) {
            uint32_t aBase = sb + ((term == 1) ? A_LO : A_HI) + aRel;
            uint32_t bBase = sb + ((term == 2) ? B_LO : B_HI) + bRel;
#pragma unroll
            for (int k16 = 0; k16 < 8; k16++) {
                uint32_t af[2][4];
                ldm_x4(af[0][0], af[0][1], af[0][2], af[0][3], aBase + k16 * 32);
                ldm_x4(af[1][0], af[1][1], af[1][2], af[1][3], aBase + 16 * TSTRIDE + k16 * 32);
                uint32_t bf[4][4];
#pragma unroll
                for (int nb = 0; nb < 4; nb++)
                    ldm_x4(bf[nb][0], bf[nb][1], bf[nb][2], bf[nb][3],
                           bBase + nb * 16 * TSTRIDE + k16 * 32);
#pragma unroll
                for (int mt = 0; mt < 2; mt++)
#pragma unroll
                    for (int nb = 0; nb < 4; nb++) {
                        mma_bf16(acc[mt][nb * 2][0], acc[mt][nb * 2][1],
                                 acc[mt][nb * 2][2], acc[mt][nb * 2][3],
                                 af[mt][0], af[mt][1], af[mt][2], af[mt][3],
                                 bf[nb][0], bf[nb][1]);
                        mma_bf16(acc[mt][nb * 2 + 1][0], acc[mt][nb * 2 + 1][1],
                                 acc[mt][nb * 2 + 1][2], acc[mt][nb * 2 + 1][3],
                                 af[mt][0], af[mt][1], af[mt][2], af[mt][3],
                                 bf[nb][2], bf[nb][3]);
                    }
            }
        }

        // ---- epilogue ----
        const float* bias = (m == 0) ? bQ : (m == 1) ? bK : bV;
#pragma unroll
        for (int nt = 0; nt < 8; nt++) {
            int col = wn * 64 + nt * 8 + (lane & 3) * 2;
            float b0 = bias[col], b1 = bias[col + 1];
#pragma unroll
            for (int mt = 0; mt < 2; mt++) {
                int row = t * 128 + wm * 32 + mt * 16 + (lane >> 2);
#pragma unroll
                for (int half = 0; half < 2; half++) {
                    int rr = row + half * 8;
                    if (rr >= N) continue;
                    float v0 = acc[mt][nt][2 * half] + b0;
                    float v1 = acc[mt][nt][2 * half + 1] + b1;
                    if (m == 0) {
                        *reinterpret_cast<float2*>(g_Q + (size_t)rr * 128 + col) =
                            make_float2(v0, v1);
                    } else {
                        __half2* o = reinterpret_cast<__half2*>(
                            g_KVh + (size_t)rr * 256 + (m == 2 ? 128 : 0) + col);
                        *o = __floats2half2_rn(v0, v1);
                    }
                }
            }
        }
        __syncthreads();
    }
}

// ============================================================
// CSR construction (hist/scatter vectorized: 4 edges/thread)
// ============================================================
__global__ void zero_cnt(int N) {
    int i = blockIdx.x * 256 + threadIdx.x;
    if (i <= N) g_cnt[i] = 0;
}

__global__ void hist_k(const int* __restrict__ dst, int E) {
    int i = blockIdx.x * 256 + threadIdx.x;
    int base = i * 4;
    if (base + 3 < E) {
        int4 d = *reinterpret_cast<const int4*>(dst + base);
        atomicAdd(&g_cnt[d.x], 1);
        atomicAdd(&g_cnt[d.y], 1);
        atomicAdd(&g_cnt[d.z], 1);
        atomicAdd(&g_cnt[d.w], 1);
    } else {
        for (int j = base; j < E; j++) atomicAdd(&g_cnt[dst[j]], 1);
    }
}

__device__ __forceinline__ int warp_incl_scan(int v, int lane) {
#pragma unroll
    for (int off = 1; off < 32; off <<= 1) {
        int t = __shfl_up_sync(0xffffffffu, v, off);
        if (lane >= off) v += t;
    }
    return v;
}

__global__ void scan_partial(int N) {
    __shared__ int wsum[32];
    int tid = threadIdx.x, lane = tid & 31, wid = tid >> 5;
    int idx = blockIdx.x * 1024 + tid;
    int x = (idx < N) ? g_cnt[idx] : 0;
    int v = warp_incl_scan(x, lane);
    if (lane == 31) wsum[wid] = v;
    __syncthreads();
    if (wid == 0) wsum[lane] = warp_incl_scan(wsum[lane], lane);
    __syncthreads();
    int incl = v + (wid > 0 ? wsum[wid - 1] : 0);
    if (idx < N) g_row[idx] = incl - x;
    if (tid == 1023) g_bsum[blockIdx.x] = incl;
}

__global__ void scan_mid(int nb, int N) {
    __shared__ int wsum[32];
    int tid = threadIdx.x, lane = tid & 31, wid = tid >> 5;
    int x = (tid < nb) ? g_bsum[tid] : 0;
    int v = warp_incl_scan(x, lane);
    if (lane == 31) wsum[wid] = v;
    __syncthreads();
    if (wid == 0) wsum[lane] = warp_incl_scan(wsum[lane], lane);
    __syncthreads();
    int incl = v + (wid > 0 ? wsum[wid - 1] : 0);
    if (tid < nb) g_boff[tid] = incl - x;
    if (tid == nb - 1) g_row[N] = incl;
}

__global__ void scan_add(int N) {
    int idx = blockIdx.x * 1024 + threadIdx.x;
    if (idx < N) {
        int v = g_row[idx] + g_boff[blockIdx.x];
        g_row[idx] = v;
        g_cur[idx] = v;
    }
}

__global__ void scatter_k(const int* __restrict__ src, const int* __restrict__ dst, int E) {
    int i = blockIdx.x * 256 + threadIdx.x;
    int base = i * 4;
    if (base + 3 < E) {
        int4 s = *reinterpret_cast<const int4*>(src + base);
        int4 d = *reinterpret_cast<const int4*>(dst + base);
        int p0 = atomicAdd(&g_cur[d.x], 1);
        int p1 = atomicAdd(&g_cur[d.y], 1);
        int p2 = atomicAdd(&g_cur[d.z], 1);
        int p3 = atomicAdd(&g_cur[d.w], 1);
        g_srcs[p0] = s.x;
        g_srcs[p1] = s.y;
        g_srcs[p2] = s.z;
        g_srcs[p3] = s.w;
    } else {
        for (int j = base; j < E; j++) {
            int pos = atomicAdd(&g_cur[dst[j]], 1);
            g_srcs[pos] = src[j];
        }
    }
}

// ============================================================
// Gather attention: one warp per dst node, fp16 KV
// ============================================================
__global__ void gather_attn(float* __restrict__ out, int N) {
    int w = (blockIdx.x * blockDim.x + threadIdx.x) >> 5;
    int lane = threadIdx.x & 31;
    if (w >= N) return;

    const float4 q = reinterpret_cast<const float4*>(g_Q)[(size_t)w * 32 + lane];
    int beg = g_row[w], end = g_row[w + 1];

    float ax = 0.f, ay = 0.f, az = 0.f, aw = 0.f, z = 0.f;
    const uint2* KV = reinterpret_cast<const uint2*>(g_KVh);

    int i = beg;
    for (; i + 1 < end; i += 2) {
        int s0 = g_srcs[i], s1 = g_srcs[i + 1];
        const uint2* p0 = KV + (size_t)s0 * 64;
        const uint2* p1 = KV + (size_t)s1 * 64;
        uint2 kr0 = p0[lane];
        uint2 kr1 = p1[lane];
        float2 k0a = __half22float2(*reinterpret_cast<__half2*>(&kr0.x));
        float2 k0b = __half22float2(*reinterpret_cast<__half2*>(&kr0.y));
        float2 k1a = __half22float2(*reinterpret_cast<__half2*>(&kr1.x));
        float2 k1b = __half22float2(*reinterpret_cast<__half2*>(&kr1.y));
        float d0 = k0a.x * q.x + k0a.y * q.y + k0b.x * q.z + k0b.y * q.w;
        float d1 = k1a.x * q.x + k1a.y * q.y + k1b.x * q.z + k1b.y * q.w;
        d0 += __shfl_xor_sync(0xffffffffu, d0, 1);
        d0 += __shfl_xor_sync(0xffffffffu, d0, 2);
        d1 += __shfl_xor_sync(0xffffffffu, d1, 1);
        d1 += __shfl_xor_sync(0xffffffffu, d1, 2);
        float e0 = __expf(fminf(5.f, fmaxf(-5.f, d0 * 0.25f)));
        float e1 = __expf(fminf(5.f, fmaxf(-5.f, d1 * 0.25f)));
        uint2 vr0 = p0[32 + lane];
        uint2 vr1 = p1[32 + lane];
        float2 v0a = __half22float2(*reinterpret_cast<__half2*>(&vr0.x));
        float2 v0b = __half22float2(*reinterpret_cast<__half2*>(&vr0.y));
        float2 v1a = __half22float2(*reinterpret_cast<__half2*>(&vr1.x));
        float2 v1b = __half22float2(*reinterpret_cast<__half2*>(&vr1.y));
        z  += e0 + e1;
        ax += v0a.x * e0 + v1a.x * e1;
        ay += v0a.y * e0 + v1a.y * e1;
        az += v0b.x * e0 + v1b.x * e1;
        aw += v0b.y * e0 + v1b.y * e1;
    }
    if (i < end) {
        int s0 = g_srcs[i];
        const uint2* p0 = KV + (size_t)s0 * 64;
        uint2 kr0 = p0[lane];
        float2 k0a = __half22float2(*reinterpret_cast<__half2*>(&kr0.x));
        float2 k0b = __half22float2(*reinterpret_cast<__half2*>(&kr0.y));
        float d0 = k0a.x * q.x + k0a.y * q.y + k0b.x * q.z + k0b.y * q.w;
        d0 += __shfl_xor_sync(0xffffffffu, d0, 1);
        d0 += __shfl_xor_sync(0xffffffffu, d0, 2);
        float e0 = __expf(fminf(5.f, fmaxf(-5.f, d0 * 0.25f)));
        uint2 vr0 = p0[32 + lane];
        float2 v0a = __half22float2(*reinterpret_cast<__half2*>(&vr0.x));
        float2 v0b = __half22float2(*reinterpret_cast<__half2*>(&vr0.y));
        z  += e0;
        ax += v0a.x * e0;
        ay += v0a.y * e0;
        az += v0b.x * e0;
        aw += v0b.y * e0;
    }

    float inv = (z > 0.f) ? 1.f / z : 0.f;
    reinterpret_cast<float4*>(out)[(size_t)w * 32 + lane] =
        make_float4(ax * inv, ay * inv, az * inv, aw * inv);
}

// ============================================================
extern "C" void kernel_launch(void* const* d_in, const int* in_sizes, int n_in,
                              void* d_out, int out_size) {
    const float* h  = (const float*)d_in[0];
    const int*   src = (const int*)d_in[1];
    const int*   dst = (const int*)d_in[2];
    const float* WQ = (const float*)d_in[3];
    const float* bQ = (const float*)d_in[4];
    const float* WK = (const float*)d_in[5];
    const float* bK = (const float*)d_in[6];
    const float* WV = (const float*)d_in[7];
    const float* bV = (const float*)d_in[8];
    int N = in_sizes[0] / INDIM;
    int E = in_sizes[1];
    int NT = (N + 127) / 128;

    cudaFuncSetAttribute(qkv_hmma, cudaFuncAttributeMaxDynamicSharedMemorySize, SM_TOTAL);
    cudaFuncSetAttribute(conv_W, cudaFuncAttributeMaxDynamicSharedMemorySize, 128 * 132 * 4);

    // fork: CSR chain on s2, QKV chain on default stream, join before gather.
    // (host-side object creation only; not destroyed — a handful of calls total,
    //  no device-memory allocation involved)
    cudaStream_t s2;
    cudaStreamCreateWithFlags(&s2, cudaStreamNonBlocking);
    cudaEvent_t evF, evJ;
    cudaEventCreateWithFlags(&evF, cudaEventDisableTiming);
    cudaEventCreateWithFlags(&evJ, cudaEventDisableTiming);

    cudaEventRecord(evF, 0);
    cudaStreamWaitEvent(s2, evF, 0);

    // --- s2: CSR chain ---
    int E4 = (E + 3) / 4;
    zero_cnt<<<(N + 1 + 255) / 256, 256, 0, s2>>>(N);
    hist_k<<<(E4 + 255) / 256, 256, 0, s2>>>(dst, E);
    int nb = (N + 1023) / 1024;
    scan_partial<<<nb, 1024, 0, s2>>>(N);
    scan_mid<<<1, 1024, 0, s2>>>(nb, N);
    scan_add<<<nb, 1024, 0, s2>>>(N);
    scatter_k<<<(E4 + 255) / 256, 256, 0, s2>>>(src, dst, E);
    cudaEventRecord(evJ, s2);

    // --- default stream: QKV chain ---
    conv_W<<<3, 256, 128 * 132 * 4>>>(WQ, WK, WV);
    qkv_hmma<<<NT, 256, SM_TOTAL>>>(h, bQ, bK, bV, N);

    cudaStreamWaitEvent(0, evJ, 0);
    gather_attn<<<(N + 7) / 8, 256>>>((float*)d_out, N);
}

// round 6
// speedup vs baseline: 2.1134x; 1.0114x over previous
#include <cuda_runtime.h>
#include <cuda_bf16.h>
#include <cuda_fp16.h>
#include <cstdint>

#define NMAX 50000
#define EMAX 800000
#define INDIM 128
#define ODIM 128

// ---- device scratch (no cudaMalloc allowed) ----
__device__ float  g_Q[NMAX * ODIM];            // Q[n][128] fp32
// per node 512B: 32 chunks of 16B; chunk l = {K[4l..4l+3] | V[4l..4l+3]} fp16
__device__ __half g_KVh[NMAX * 2 * ODIM];
__device__ unsigned char g_WThi[3][34816];     // W^T bf16 hi, padded stride 272B
__device__ unsigned char g_WTlo[3][34816];     // W^T bf16 lo
__device__ int   g_cnt[NMAX + 1];
__device__ int   g_row[NMAX + 1];
__device__ int   g_cur[NMAX];
__device__ int   g_srcs[EMAX];
__device__ int   g_bsum[64];
__device__ int   g_boff[64];

// ============================================================
// helpers
// ============================================================
__device__ __forceinline__ uint32_t smem_u32(const void* p) {
    uint32_t a;
    asm("{ .reg .u64 t; cvta.to.shared.u64 t, %1; cvt.u32.u64 %0, t; }" : "=r"(a) : "l"(p));
    return a;
}
__device__ __forceinline__ void ldm_x4(uint32_t& r0, uint32_t& r1, uint32_t& r2,
                                       uint32_t& r3, uint32_t addr) {
    asm volatile("ldmatrix.sync.aligned.m8n8.x4.shared.b16 {%0,%1,%2,%3}, [%4];"
                 : "=r"(r0), "=r"(r1), "=r"(r2), "=r"(r3) : "r"(addr));
}
__device__ __forceinline__ void mma_bf16(float& c0, float& c1, float& c2, float& c3,
                                         uint32_t a0, uint32_t a1, uint32_t a2, uint32_t a3,
                                         uint32_t b0, uint32_t b1) {
    asm volatile("mma.sync.aligned.m16n8k16.row.col.f32.bf16.bf16.f32 "
                 "{%0,%1,%2,%3}, {%4,%5,%6,%7}, {%8,%9}, {%0,%1,%2,%3};"
                 : "+f"(c0), "+f"(c1), "+f"(c2), "+f"(c3)
                 : "r"(a0), "r"(a1), "r"(a2), "r"(a3), "r"(b0), "r"(b1));
}

// smem tile layout: row stride 136 bf16 = 272 B
#define TSTRIDE 272
#define A_HI 0
#define A_LO 34816
#define B_HI 69632
#define B_LO 104448
#define SM_TOTAL 139264

// ============================================================
// W^T conversion to bf16 hi/lo (once): 3 CTAs, smem transpose
// ============================================================
__global__ void conv_W(const float* __restrict__ WQ, const float* __restrict__ WK,
                       const float* __restrict__ WV) {
    extern __shared__ float ws[];               // 128 x 132 floats
    int m = blockIdx.x, tid = threadIdx.x;
    const float* W = (m == 0) ? WQ : (m == 1) ? WK : WV;

    for (int i = tid; i < 4096; i += 256) {
        int r = i >> 5, c4 = i & 31;
        float4 v = reinterpret_cast<const float4*>(W)[r * 32 + c4];
        *reinterpret_cast<float4*>(ws + r * 132 + c4 * 4) = v;
    }
    __syncthreads();

    int n = tid >> 1, kh = tid & 1;
#pragma unroll
    for (int i = 0; i < 8; i++) {
        int k0 = kh * 64 + i * 8;
        uint32_t hw[4], lw[4];
#pragma unroll
        for (int p = 0; p < 4; p++) {
            float xa = ws[(k0 + 2 * p) * 132 + n];
            float xb = ws[(k0 + 2 * p + 1) * 132 + n];
            __nv_bfloat16 a = __float2bfloat16(xa);
            __nv_bfloat16 b = __float2bfloat16(xb);
            __nv_bfloat16 la = __float2bfloat16(xa - __bfloat162float(a));
            __nv_bfloat16 lb = __float2bfloat16(xb - __bfloat162float(b));
            hw[p] = (uint32_t)__bfloat16_as_ushort(a) | ((uint32_t)__bfloat16_as_ushort(b) << 16);
            lw[p] = (uint32_t)__bfloat16_as_ushort(la) | ((uint32_t)__bfloat16_as_ushort(lb) << 16);
        }
        *reinterpret_cast<uint4*>(g_WThi[m] + n * TSTRIDE + k0 * 2) =
            make_uint4(hw[0], hw[1], hw[2], hw[3]);
        *reinterpret_cast<uint4*>(g_WTlo[m] + n * TSTRIDE + k0 * 2) =
            make_uint4(lw[0], lw[1], lw[2], lw[3]);
    }
}

// ============================================================
// QKV GEMM: one CTA per 128-node tile; loops m = Q,K,V.
// K/V stored fp16, lane-interleaved (see g_KVh layout comment).
// ============================================================
__global__ void __launch_bounds__(256, 1)
qkv_hmma(const float* __restrict__ h,
         const float* __restrict__ bQ, const float* __restrict__ bK,
         const float* __restrict__ bV, int N) {
    extern __shared__ char smem[];
    uint32_t sb = smem_u32(smem);
    int tid = threadIdx.x;
    int t = blockIdx.x;

    // ---- convert h tile [128 x 128] -> A_hi/A_lo (once) ----
    {
        int r = tid >> 1, half = tid & 1;
        int node = t * 128 + r;
        const float4* hp = reinterpret_cast<const float4*>(h + (size_t)node * 128);
#pragma unroll
        for (int i = 0; i < 16; i++) {
            int c = half * 64 + i * 4;
            float4 x = make_float4(0.f, 0.f, 0.f, 0.f);
            if (node < N) x = hp[c >> 2];
            uint32_t ua = __float_as_uint(x.x), ub = __float_as_uint(x.y);
            uint32_t uc = __float_as_uint(x.z), ud = __float_as_uint(x.w);
            uint32_t h0 = __byte_perm(ua, ub, 0x7632);
            uint32_t h1 = __byte_perm(uc, ud, 0x7632);
            float la = x.x - __uint_as_float(ua & 0xFFFF0000u);
            float lb = x.y - __uint_as_float(ub & 0xFFFF0000u);
            float lc = x.z - __uint_as_float(uc & 0xFFFF0000u);
            float ld = x.w - __uint_as_float(ud & 0xFFFF0000u);
            uint32_t l0, l1;
            asm("cvt.rn.bf16x2.f32 %0, %1, %2;" : "=r"(l0) : "f"(lb), "f"(la));
            asm("cvt.rn.bf16x2.f32 %0, %1, %2;" : "=r"(l1) : "f"(ld), "f"(lc));
            *reinterpret_cast<uint2*>(smem + A_HI + r * TSTRIDE + c * 2) = make_uint2(h0, h1);
            *reinterpret_cast<uint2*>(smem + A_LO + r * TSTRIDE + c * 2) = make_uint2(l0, l1);
        }
    }

    int wid = tid >> 5, lane = tid & 31;
    int wm = wid & 3, wn = wid >> 2;
    uint32_t aRel = (uint32_t)((wm * 32 + (lane & 15)) * TSTRIDE + (lane >> 4) * 16);
    uint32_t bRel = (uint32_t)((wn * 64 + (lane & 7) + ((lane >> 4) << 3)) * TSTRIDE +
                               (((lane >> 3) & 1) << 4));

    for (int m = 0; m < 3; m++) {
        {
            const uint4* sH = reinterpret_cast<const uint4*>(g_WThi[m]);
            const uint4* sL = reinterpret_cast<const uint4*>(g_WTlo[m]);
            uint4* dH = reinterpret_cast<uint4*>(smem + B_HI);
            uint4* dL = reinterpret_cast<uint4*>(smem + B_LO);
            for (int i = tid; i < 2176; i += 256) {
                dH[i] = sH[i];
                dL[i] = sL[i];
            }
        }
        __syncthreads();

        float acc[2][8][4];
#pragma unroll
        for (int mt = 0; mt < 2; mt++)
#pragma unroll
            for (int nt = 0; nt < 8; nt++)
#pragma unroll
                for (int q = 0; q < 4; q++) acc[mt][nt][q] = 0.f;

#pragma unroll
        for (int term = 0; term < 3; term++) {
            uint32_t aBase = sb + ((term == 1) ? A_LO : A_HI) + aRel;
            uint32_t bBase = sb + ((term == 2) ? B_LO : B_HI) + bRel;
#pragma unroll
            for (int k16 = 0; k16 < 8; k16++) {
                uint32_t af[2][4];
                ldm_x4(af[0][0], af[0][1], af[0][2], af[0][3], aBase + k16 * 32);
                ldm_x4(af[1][0], af[1][1], af[1][2], af[1][3], aBase + 16 * TSTRIDE + k16 * 32);
                uint32_t bf[4][4];
#pragma unroll
                for (int nb = 0; nb < 4; nb++)
                    ldm_x4(bf[nb][0], bf[nb][1], bf[nb][2], bf[nb][3],
                           bBase + nb * 16 * TSTRIDE + k16 * 32);
#pragma unroll
                for (int mt = 0; mt < 2; mt++)
#pragma unroll
                    for (int nb = 0; nb < 4; nb++) {
                        mma_bf16(acc[mt][nb * 2][0], acc[mt][nb * 2][1],
                                 acc[mt][nb * 2][2], acc[mt][nb * 2][3],
                                 af[mt][0], af[mt][1], af[mt][2], af[mt][3],
                                 bf[nb][0], bf[nb][1]);
                        mma_bf16(acc[mt][nb * 2 + 1][0], acc[mt][nb * 2 + 1][1],
                                 acc[mt][nb * 2 + 1][2], acc[mt][nb * 2 + 1][3],
                                 af[mt][0], af[mt][1], af[mt][2], af[mt][3],
                                 bf[nb][2], bf[nb][3]);
                    }
            }
        }

        // ---- epilogue: Q fp32; K/V fp16 interleaved chunks ----
        const float* bias = (m == 0) ? bQ : (m == 1) ? bK : bV;
        char* kvb = reinterpret_cast<char*>(g_KVh);
#pragma unroll
        for (int nt = 0; nt < 8; nt++) {
            int col = wn * 64 + nt * 8 + (lane & 3) * 2;
            float b0 = bias[col], b1 = bias[col + 1];
#pragma unroll
            for (int mt = 0; mt < 2; mt++) {
                int row = t * 128 + wm * 32 + mt * 16 + (lane >> 2);
#pragma unroll
                for (int half = 0; half < 2; half++) {
                    int rr = row + half * 8;
                    if (rr >= N) continue;
                    float v0 = acc[mt][nt][2 * half] + b0;
                    float v1 = acc[mt][nt][2 * half + 1] + b1;
                    if (m == 0) {
                        *reinterpret_cast<float2*>(g_Q + (size_t)rr * 128 + col) =
                            make_float2(v0, v1);
                    } else {
                        // chunk = col>>2 (16B), K at +0, V at +8, inner (col&3)*2
                        __half2* o = reinterpret_cast<__half2*>(
                            kvb + (size_t)rr * 512 + (col >> 2) * 16 +
                            (m == 2 ? 8 : 0) + (col & 3) * 2);
                        *o = __floats2half2_rn(v0, v1);
                    }
                }
            }
        }
        __syncthreads();
    }
}

// ============================================================
// CSR construction
// ============================================================
__global__ void zero_cnt(int N) {
    int i = blockIdx.x * 256 + threadIdx.x;
    if (i <= N) g_cnt[i] = 0;
}

__global__ void hist_k(const int* __restrict__ dst, int E) {
    int i = blockIdx.x * 256 + threadIdx.x;
    int base = i * 4;
    if (base + 3 < E) {
        int4 d = *reinterpret_cast<const int4*>(dst + base);
        atomicAdd(&g_cnt[d.x], 1);
        atomicAdd(&g_cnt[d.y], 1);
        atomicAdd(&g_cnt[d.z], 1);
        atomicAdd(&g_cnt[d.w], 1);
    } else {
        for (int j = base; j < E; j++) atomicAdd(&g_cnt[dst[j]], 1);
    }
}

__device__ __forceinline__ int warp_incl_scan(int v, int lane) {
#pragma unroll
    for (int off = 1; off < 32; off <<= 1) {
        int t = __shfl_up_sync(0xffffffffu, v, off);
        if (lane >= off) v += t;
    }
    return v;
}

__global__ void scan_partial(int N) {
    __shared__ int wsum[32];
    int tid = threadIdx.x, lane = tid & 31, wid = tid >> 5;
    int idx = blockIdx.x * 1024 + tid;
    int x = (idx < N) ? g_cnt[idx] : 0;
    int v = warp_incl_scan(x, lane);
    if (lane == 31) wsum[wid] = v;
    __syncthreads();
    if (wid == 0) wsum[lane] = warp_incl_scan(wsum[lane], lane);
    __syncthreads();
    int incl = v + (wid > 0 ? wsum[wid - 1] : 0);
    if (idx < N) g_row[idx] = incl - x;
    if (tid == 1023) g_bsum[blockIdx.x] = incl;
}

// 64 threads: scan up to 64 block sums (nb <= 49)
__global__ void scan_mid(int nb, int N) {
    __shared__ int w0sum;
    int tid = threadIdx.x, lane = tid & 31, wid = tid >> 5;
    int x = (tid < nb) ? g_bsum[tid] : 0;
    int v = warp_incl_scan(x, lane);
    if (wid == 0 && lane == 31) w0sum = v;
    __syncthreads();
    int incl = v + (wid == 1 ? w0sum : 0);
    if (tid < nb) g_boff[tid] = incl - x;
    if (tid == nb - 1) g_row[N] = incl;
}

__global__ void scan_add(int N) {
    int idx = blockIdx.x * 1024 + threadIdx.x;
    if (idx < N) {
        int v = g_row[idx] + g_boff[blockIdx.x];
        g_row[idx] = v;
        g_cur[idx] = v;
    }
}

__global__ void scatter_k(const int* __restrict__ src, const int* __restrict__ dst, int E) {
    int i = blockIdx.x * 256 + threadIdx.x;
    int base = i * 4;
    if (base + 3 < E) {
        int4 s = *reinterpret_cast<const int4*>(src + base);
        int4 d = *reinterpret_cast<const int4*>(dst + base);
        int p0 = atomicAdd(&g_cur[d.x], 1);
        int p1 = atomicAdd(&g_cur[d.y], 1);
        int p2 = atomicAdd(&g_cur[d.z], 1);
        int p3 = atomicAdd(&g_cur[d.w], 1);
        g_srcs[p0] = s.x;
        g_srcs[p1] = s.y;
        g_srcs[p2] = s.z;
        g_srcs[p3] = s.w;
    } else {
        for (int j = base; j < E; j++) {
            int pos = atomicAdd(&g_cur[dst[j]], 1);
            g_srcs[pos] = src[j];
        }
    }
}

// ============================================================
// Gather attention: one warp per dst node, interleaved fp16 KV,
// one uint4 per edge per lane, 4-edge unroll.
// ============================================================
__global__ void gather_attn(float* __restrict__ out, int N) {
    int w = (blockIdx.x * blockDim.x + threadIdx.x) >> 5;
    int lane = threadIdx.x & 31;
    if (w >= N) return;

    const float4 q = reinterpret_cast<const float4*>(g_Q)[(size_t)w * 32 + lane];
    int beg = g_row[w], end = g_row[w + 1];

    float ax = 0.f, ay = 0.f, az = 0.f, aw = 0.f, z = 0.f;
    const uint4* KV = reinterpret_cast<const uint4*>(g_KVh);

    int i = beg;
    for (; i + 3 < end; i += 4) {
        int ss[4];
#pragma unroll
        for (int j = 0; j < 4; j++) ss[j] = g_srcs[i + j];
        uint4 kv[4];
#pragma unroll
        for (int j = 0; j < 4; j++) kv[j] = KV[(size_t)ss[j] * 32 + lane];
        float ee[4];
#pragma unroll
        for (int j = 0; j < 4; j++) {
            float2 ka = __half22float2(*reinterpret_cast<__half2*>(&kv[j].x));
            float2 kb = __half22float2(*reinterpret_cast<__half2*>(&kv[j].y));
            float d = ka.x * q.x + ka.y * q.y + kb.x * q.z + kb.y * q.w;
            d += __shfl_xor_sync(0xffffffffu, d, 1);
            d += __shfl_xor_sync(0xffffffffu, d, 2);
            ee[j] = __expf(fminf(5.f, fmaxf(-5.f, d * 0.25f)));
        }
#pragma unroll
        for (int j = 0; j < 4; j++) {
            float2 va = __half22float2(*reinterpret_cast<__half2*>(&kv[j].z));
            float2 vb = __half22float2(*reinterpret_cast<__half2*>(&kv[j].w));
            z  += ee[j];
            ax += va.x * ee[j];
            ay += va.y * ee[j];
            az += vb.x * ee[j];
            aw += vb.y * ee[j];
        }
    }
    for (; i < end; i++) {
        uint4 kv = KV[(size_t)g_srcs[i] * 32 + lane];
        float2 ka = __half22float2(*reinterpret_cast<__half2*>(&kv.x));
        float2 kb = __half22float2(*reinterpret_cast<__half2*>(&kv.y));
        float d = ka.x * q.x + ka.y * q.y + kb.x * q.z + kb.y * q.w;
        d += __shfl_xor_sync(0xffffffffu, d, 1);
        d += __shfl_xor_sync(0xffffffffu, d, 2);
        float e = __expf(fminf(5.f, fmaxf(-5.f, d * 0.25f)));
        float2 va = __half22float2(*reinterpret_cast<__half2*>(&kv.z));
        float2 vb = __half22float2(*reinterpret_cast<__half2*>(&kv.w));
        z  += e;
        ax += va.x * e;
        ay += va.y * e;
        az += vb.x * e;
        aw += vb.y * e;
    }

    float inv = (z > 0.f) ? 1.f / z : 0.f;
    reinterpret_cast<float4*>(out)[(size_t)w * 32 + lane] =
        make_float4(ax * inv, ay * inv, az * inv, aw * inv);
}

// ============================================================
extern "C" void kernel_launch(void* const* d_in, const int* in_sizes, int n_in,
                              void* d_out, int out_size) {
    const float* h  = (const float*)d_in[0];
    const int*   src = (const int*)d_in[1];
    const int*   dst = (const int*)d_in[2];
    const float* WQ = (const float*)d_in[3];
    const float* bQ = (const float*)d_in[4];
    const float* WK = (const float*)d_in[5];
    const float* bK = (const float*)d_in[6];
    const float* WV = (const float*)d_in[7];
    const float* bV = (const float*)d_in[8];
    int N = in_sizes[0] / INDIM;
    int E = in_sizes[1];
    int NT = (N + 127) / 128;

    cudaFuncSetAttribute(qkv_hmma, cudaFuncAttributeMaxDynamicSharedMemorySize, SM_TOTAL);
    cudaFuncSetAttribute(conv_W, cudaFuncAttributeMaxDynamicSharedMemorySize, 128 * 132 * 4);

    cudaStream_t s2;
    cudaStreamCreateWithFlags(&s2, cudaStreamNonBlocking);
    cudaEvent_t evF, evJ;
    cudaEventCreateWithFlags(&evF, cudaEventDisableTiming);
    cudaEventCreateWithFlags(&evJ, cudaEventDisableTiming);

    cudaEventRecord(evF, 0);
    cudaStreamWaitEvent(s2, evF, 0);

    // --- s2: CSR chain ---
    int E4 = (E + 3) / 4;
    zero_cnt<<<(N + 1 + 255) / 256, 256, 0, s2>>>(N);
    hist_k<<<(E4 + 255) / 256, 256, 0, s2>>>(dst, E);
    int nb = (N + 1023) / 1024;
    scan_partial<<<nb, 1024, 0, s2>>>(N);
    scan_mid<<<1, 64, 0, s2>>>(nb, N);
    scan_add<<<nb, 1024, 0, s2>>>(N);
    scatter_k<<<(E4 + 255) / 256, 256, 0, s2>>>(src, dst, E);
    cudaEventRecord(evJ, s2);

    // --- default stream: QKV chain ---
    conv_W<<<3, 256, 128 * 132 * 4>>>(WQ, WK, WV);
    qkv_hmma<<<NT, 256, SM_TOTAL>>>(h, bQ, bK, bV, N);

    cudaStreamWaitEvent(0, evJ, 0);
    gather_attn<<<(N + 7) / 8, 256>>>((float*)d_out, N);
}

// round 7
// speedup vs baseline: 2.1549x; 1.0196x over previous
#include <cuda_runtime.h>
#include <cuda_bf16.h>
#include <cuda_fp16.h>
#include <cstdint>

#define NMAX 50000
#define EMAX 800000
#define INDIM 128
#define ODIM 128

// ---- device scratch (no cudaMalloc allowed) ----
__device__ float  g_Q[NMAX * ODIM];            // Q[n][128] fp32
// per node 512B: 32 chunks of 16B; chunk l = {K[4l..4l+3] | V[4l..4l+3]} fp16
__device__ __half g_KVh[NMAX * 2 * ODIM];
__device__ unsigned char g_WThi[3][34816];     // W^T bf16 hi, padded stride 272B
__device__ unsigned char g_WTlo[3][34816];     // W^T bf16 lo
__device__ int   g_cnt[NMAX + 1];              // BSS-zero; re-zeroed by scan_partial
__device__ int   g_row[NMAX + 1];
__device__ int   g_cur[NMAX];
__device__ int   g_srcs[EMAX];
__device__ int   g_bsum[64];

// ============================================================
// helpers
// ============================================================
__device__ __forceinline__ uint32_t smem_u32(const void* p) {
    uint32_t a;
    asm("{ .reg .u64 t; cvta.to.shared.u64 t, %1; cvt.u32.u64 %0, t; }" : "=r"(a) : "l"(p));
    return a;
}
__device__ __forceinline__ void ldm_x4(uint32_t& r0, uint32_t& r1, uint32_t& r2,
                                       uint32_t& r3, uint32_t addr) {
    asm volatile("ldmatrix.sync.aligned.m8n8.x4.shared.b16 {%0,%1,%2,%3}, [%4];"
                 : "=r"(r0), "=r"(r1), "=r"(r2), "=r"(r3) : "r"(addr));
}
__device__ __forceinline__ void mma_bf16(float& c0, float& c1, float& c2, float& c3,
                                         uint32_t a0, uint32_t a1, uint32_t a2, uint32_t a3,
                                         uint32_t b0, uint32_t b1) {
    asm volatile("mma.sync.aligned.m16n8k16.row.col.f32.bf16.bf16.f32 "
                 "{%0,%1,%2,%3}, {%4,%5,%6,%7}, {%8,%9}, {%0,%1,%2,%3};"
                 : "+f"(c0), "+f"(c1), "+f"(c2), "+f"(c3)
                 : "r"(a0), "r"(a1), "r"(a2), "r"(a3), "r"(b0), "r"(b1));
}

// smem tile layout: row stride 136 bf16 = 272 B
#define TSTRIDE 272
#define A_HI 0
#define A_LO 34816
#define B_HI 69632
#define B_LO 104448
#define SM_TOTAL 139264

// ============================================================
// W^T conversion to bf16 hi/lo (once): 3 CTAs, smem transpose
// ============================================================
__global__ void conv_W(const float* __restrict__ WQ, const float* __restrict__ WK,
                       const float* __restrict__ WV) {
    extern __shared__ float ws[];               // 128 x 132 floats
    int m = blockIdx.x, tid = threadIdx.x;
    const float* W = (m == 0) ? WQ : (m == 1) ? WK : WV;

    for (int i = tid; i < 4096; i += 256) {
        int r = i >> 5, c4 = i & 31;
        float4 v = reinterpret_cast<const float4*>(W)[r * 32 + c4];
        *reinterpret_cast<float4*>(ws + r * 132 + c4 * 4) = v;
    }
    __syncthreads();

    int n = tid >> 1, kh = tid & 1;
#pragma unroll
    for (int i = 0; i < 8; i++) {
        int k0 = kh * 64 + i * 8;
        uint32_t hw[4], lw[4];
#pragma unroll
        for (int p = 0; p < 4; p++) {
            float xa = ws[(k0 + 2 * p) * 132 + n];
            float xb = ws[(k0 + 2 * p + 1) * 132 + n];
            __nv_bfloat16 a = __float2bfloat16(xa);
            __nv_bfloat16 b = __float2bfloat16(xb);
            __nv_bfloat16 la = __float2bfloat16(xa - __bfloat162float(a));
            __nv_bfloat16 lb = __float2bfloat16(xb - __bfloat162float(b));
            hw[p] = (uint32_t)__bfloat16_as_ushort(a) | ((uint32_t)__bfloat16_as_ushort(b) << 16);
            lw[p] = (uint32_t)__bfloat16_as_ushort(la) | ((uint32_t)__bfloat16_as_ushort(lb) << 16);
        }
        *reinterpret_cast<uint4*>(g_WThi[m] + n * TSTRIDE + k0 * 2) =
            make_uint4(hw[0], hw[1], hw[2], hw[3]);
        *reinterpret_cast<uint4*>(g_WTlo[m] + n * TSTRIDE + k0 * 2) =
            make_uint4(lw[0], lw[1], lw[2], lw[3]);
    }
}

// ============================================================
// QKV GEMM: one CTA per 128-node tile; loops m = Q,K,V.
// ============================================================
__global__ void __launch_bounds__(256, 1)
qkv_hmma(const float* __restrict__ h,
         const float* __restrict__ bQ, const float* __restrict__ bK,
         const float* __restrict__ bV, int N) {
    extern __shared__ char smem[];
    uint32_t sb = smem_u32(smem);
    int tid = threadIdx.x;
    int t = blockIdx.x;

    // ---- convert h tile [128 x 128] -> A_hi/A_lo (once) ----
    {
        int r = tid >> 1, half = tid & 1;
        int node = t * 128 + r;
        const float4* hp = reinterpret_cast<const float4*>(h + (size_t)node * 128);
#pragma unroll
        for (int i = 0; i < 16; i++) {
            int c = half * 64 + i * 4;
            float4 x = make_float4(0.f, 0.f, 0.f, 0.f);
            if (node < N) x = hp[c >> 2];
            uint32_t ua = __float_as_uint(x.x), ub = __float_as_uint(x.y);
            uint32_t uc = __float_as_uint(x.z), ud = __float_as_uint(x.w);
            uint32_t h0 = __byte_perm(ua, ub, 0x7632);
            uint32_t h1 = __byte_perm(uc, ud, 0x7632);
            float la = x.x - __uint_as_float(ua & 0xFFFF0000u);
            float lb = x.y - __uint_as_float(ub & 0xFFFF0000u);
            float lc = x.z - __uint_as_float(uc & 0xFFFF0000u);
            float ld = x.w - __uint_as_float(ud & 0xFFFF0000u);
            uint32_t l0, l1;
            asm("cvt.rn.bf16x2.f32 %0, %1, %2;" : "=r"(l0) : "f"(lb), "f"(la));
            asm("cvt.rn.bf16x2.f32 %0, %1, %2;" : "=r"(l1) : "f"(ld), "f"(lc));
            *reinterpret_cast<uint2*>(smem + A_HI + r * TSTRIDE + c * 2) = make_uint2(h0, h1);
            *reinterpret_cast<uint2*>(smem + A_LO + r * TSTRIDE + c * 2) = make_uint2(l0, l1);
        }
    }

    int wid = tid >> 5, lane = tid & 31;
    int wm = wid & 3, wn = wid >> 2;
    uint32_t aRel = (uint32_t)((wm * 32 + (lane & 15)) * TSTRIDE + (lane >> 4) * 16);
    uint32_t bRel = (uint32_t)((wn * 64 + (lane & 7) + ((lane >> 4) << 3)) * TSTRIDE +
                               (((lane >> 3) & 1) << 4));

    for (int m = 0; m < 3; m++) {
        {
            const uint4* sH = reinterpret_cast<const uint4*>(g_WThi[m]);
            const uint4* sL = reinterpret_cast<const uint4*>(g_WTlo[m]);
            uint4* dH = reinterpret_cast<uint4*>(smem + B_HI);
            uint4* dL = reinterpret_cast<uint4*>(smem + B_LO);
            for (int i = tid; i < 2176; i += 256) {
                dH[i] = sH[i];
                dL[i] = sL[i];
            }
        }
        __syncthreads();

        float acc[2][8][4];
#pragma unroll
        for (int mt = 0; mt < 2; mt++)
#pragma unroll
            for (int nt = 0; nt < 8; nt++)
#pragma unroll
                for (int q = 0; q < 4; q++) acc[mt][nt][q] = 0.f;

#pragma unroll
        for (int term = 0; term < 3; term++) {
            uint32_t aBase = sb + ((term == 1) ? A_LO : A_HI) + aRel;
            uint32_t bBase = sb + ((term == 2) ? B_LO : B_HI) + bRel;
#pragma unroll
            for (int k16 = 0; k16 < 8; k16++) {
                uint32_t af[2][4];
                ldm_x4(af[0][0], af[0][1], af[0][2], af[0][3], aBase + k16 * 32);
                ldm_x4(af[1][0], af[1][1], af[1][2], af[1][3], aBase + 16 * TSTRIDE + k16 * 32);
                uint32_t bf[4][4];
#pragma unroll
                for (int nb = 0; nb < 4; nb++)
                    ldm_x4(bf[nb][0], bf[nb][1], bf[nb][2], bf[nb][3],
                           bBase + nb * 16 * TSTRIDE + k16 * 32);
#pragma unroll
                for (int mt = 0; mt < 2; mt++)
#pragma unroll
                    for (int nb = 0; nb < 4; nb++) {
                        mma_bf16(acc[mt][nb * 2][0], acc[mt][nb * 2][1],
                                 acc[mt][nb * 2][2], acc[mt][nb * 2][3],
                                 af[mt][0], af[mt][1], af[mt][2], af[mt][3],
                                 bf[nb][0], bf[nb][1]);
                        mma_bf16(acc[mt][nb * 2 + 1][0], acc[mt][nb * 2 + 1][1],
                                 acc[mt][nb * 2 + 1][2], acc[mt][nb * 2 + 1][3],
                                 af[mt][0], af[mt][1], af[mt][2], af[mt][3],
                                 bf[nb][2], bf[nb][3]);
                    }
            }
        }

        // ---- epilogue: Q fp32; K/V fp16 interleaved chunks ----
        const float* bias = (m == 0) ? bQ : (m == 1) ? bK : bV;
        char* kvb = reinterpret_cast<char*>(g_KVh);
#pragma unroll
        for (int nt = 0; nt < 8; nt++) {
            int col = wn * 64 + nt * 8 + (lane & 3) * 2;
            float b0 = bias[col], b1 = bias[col + 1];
#pragma unroll
            for (int mt = 0; mt < 2; mt++) {
                int row = t * 128 + wm * 32 + mt * 16 + (lane >> 2);
#pragma unroll
                for (int half = 0; half < 2; half++) {
                    int rr = row + half * 8;
                    if (rr >= N) continue;
                    float v0 = acc[mt][nt][2 * half] + b0;
                    float v1 = acc[mt][nt][2 * half + 1] + b1;
                    if (m == 0) {
                        *reinterpret_cast<float2*>(g_Q + (size_t)rr * 128 + col) =
                            make_float2(v0, v1);
                    } else {
                        __half2* o = reinterpret_cast<__half2*>(
                            kvb + (size_t)rr * 512 + (col >> 2) * 16 +
                            (m == 2 ? 8 : 0) + (col & 3) * 2);
                        *o = __floats2half2_rn(v0, v1);
                    }
                }
            }
        }
        __syncthreads();
    }
}

// ============================================================
// CSR construction: 4-kernel chain
// ============================================================
__global__ void hist_k(const int* __restrict__ dst, int E) {
    int i = blockIdx.x * 256 + threadIdx.x;
    int base = i * 4;
    if (base + 3 < E) {
        int4 d = *reinterpret_cast<const int4*>(dst + base);
        atomicAdd(&g_cnt[d.x], 1);
        atomicAdd(&g_cnt[d.y], 1);
        atomicAdd(&g_cnt[d.z], 1);
        atomicAdd(&g_cnt[d.w], 1);
    } else {
        for (int j = base; j < E; j++) atomicAdd(&g_cnt[dst[j]], 1);
    }
}

__device__ __forceinline__ int warp_incl_scan(int v, int lane) {
#pragma unroll
    for (int off = 1; off < 32; off <<= 1) {
        int t = __shfl_up_sync(0xffffffffu, v, off);
        if (lane >= off) v += t;
    }
    return v;
}

// block-local exclusive scan; also re-zeroes g_cnt for the next replay
__global__ void scan_partial(int N) {
    __shared__ int wsum[32];
    int tid = threadIdx.x, lane = tid & 31, wid = tid >> 5;
    int idx = blockIdx.x * 1024 + tid;
    int x = 0;
    if (idx < N) {
        x = g_cnt[idx];
        g_cnt[idx] = 0;                 // replay invariant restored here
    }
    int v = warp_incl_scan(x, lane);
    if (lane == 31) wsum[wid] = v;
    __syncthreads();
    if (wid == 0) wsum[lane] = warp_incl_scan(wsum[lane], lane);
    __syncthreads();
    int incl = v + (wid > 0 ? wsum[wid - 1] : 0);
    if (idx < N) g_row[idx] = incl - x;
    if (tid == 1023) g_bsum[blockIdx.x] = incl;
}

// adds inter-block offset (computed inline from g_bsum) and writes g_cur
__global__ void scan_add(int N, int E) {
    __shared__ int boff;
    int b = blockIdx.x, tid = threadIdx.x;
    if (tid < 32) {
        int acc = 0;
        for (int i = tid; i < b; i += 32) acc += g_bsum[i];
#pragma unroll
        for (int o = 16; o; o >>= 1) acc += __shfl_xor_sync(0xffffffffu, acc, o);
        if (tid == 0) boff = acc;
    }
    __syncthreads();
    int idx = b * 1024 + tid;
    if (idx < N) {
        int v = g_row[idx] + boff;
        g_row[idx] = v;
        g_cur[idx] = v;
    }
    if (idx == 0) g_row[N] = E;
}

__global__ void scatter_k(const int* __restrict__ src, const int* __restrict__ dst, int E) {
    int i = blockIdx.x * 256 + threadIdx.x;
    int base = i * 4;
    if (base + 3 < E) {
        int4 s = *reinterpret_cast<const int4*>(src + base);
        int4 d = *reinterpret_cast<const int4*>(dst + base);
        int p0 = atomicAdd(&g_cur[d.x], 1);
        int p1 = atomicAdd(&g_cur[d.y], 1);
        int p2 = atomicAdd(&g_cur[d.z], 1);
        int p3 = atomicAdd(&g_cur[d.w], 1);
        g_srcs[p0] = s.x;
        g_srcs[p1] = s.y;
        g_srcs[p2] = s.z;
        g_srcs[p3] = s.w;
    } else {
        for (int j = base; j < E; j++) {
            int pos = atomicAdd(&g_cur[dst[j]], 1);
            g_srcs[pos] = src[j];
        }
    }
}

// ============================================================
// Gather attention: one warp per dst node, interleaved fp16 KV
// ============================================================
__global__ void gather_attn(float* __restrict__ out, int N) {
    int w = (blockIdx.x * blockDim.x + threadIdx.x) >> 5;
    int lane = threadIdx.x & 31;
    if (w >= N) return;

    const float4 q = reinterpret_cast<const float4*>(g_Q)[(size_t)w * 32 + lane];
    int beg = g_row[w], end = g_row[w + 1];

    float ax = 0.f, ay = 0.f, az = 0.f, aw = 0.f, z = 0.f;
    const uint4* KV = reinterpret_cast<const uint4*>(g_KVh);

    int i = beg;
    for (; i + 3 < end; i += 4) {
        int ss[4];
#pragma unroll
        for (int j = 0; j < 4; j++) ss[j] = g_srcs[i + j];
        uint4 kv[4];
#pragma unroll
        for (int j = 0; j < 4; j++) kv[j] = KV[(size_t)ss[j] * 32 + lane];
        float ee[4];
#pragma unroll
        for (int j = 0; j < 4; j++) {
            float2 ka = __half22float2(*reinterpret_cast<__half2*>(&kv[j].x));
            float2 kb = __half22float2(*reinterpret_cast<__half2*>(&kv[j].y));
            float d = ka.x * q.x + ka.y * q.y + kb.x * q.z + kb.y * q.w;
            d += __shfl_xor_sync(0xffffffffu, d, 1);
            d += __shfl_xor_sync(0xffffffffu, d, 2);
            ee[j] = __expf(fminf(5.f, fmaxf(-5.f, d * 0.25f)));
        }
#pragma unroll
        for (int j = 0; j < 4; j++) {
            float2 va = __half22float2(*reinterpret_cast<__half2*>(&kv[j].z));
            float2 vb = __half22float2(*reinterpret_cast<__half2*>(&kv[j].w));
            z  += ee[j];
            ax += va.x * ee[j];
            ay += va.y * ee[j];
            az += vb.x * ee[j];
            aw += vb.y * ee[j];
        }
    }
    for (; i < end; i++) {
        uint4 kv = KV[(size_t)g_srcs[i] * 32 + lane];
        float2 ka = __half22float2(*reinterpret_cast<__half2*>(&kv.x));
        float2 kb = __half22float2(*reinterpret_cast<__half2*>(&kv.y));
        float d = ka.x * q.x + ka.y * q.y + kb.x * q.z + kb.y * q.w;
        d += __shfl_xor_sync(0xffffffffu, d, 1);
        d += __shfl_xor_sync(0xffffffffu, d, 2);
        float e = __expf(fminf(5.f, fmaxf(-5.f, d * 0.25f)));
        float2 va = __half22float2(*reinterpret_cast<__half2*>(&kv.z));
        float2 vb = __half22float2(*reinterpret_cast<__half2*>(&kv.w));
        z  += e;
        ax += va.x * e;
        ay += va.y * e;
        az += vb.x * e;
        aw += vb.y * e;
    }

    float inv = (z > 0.f) ? 1.f / z : 0.f;
    reinterpret_cast<float4*>(out)[(size_t)w * 32 + lane] =
        make_float4(ax * inv, ay * inv, az * inv, aw * inv);
}

// ============================================================
extern "C" void kernel_launch(void* const* d_in, const int* in_sizes, int n_in,
                              void* d_out, int out_size) {
    const float* h  = (const float*)d_in[0];
    const int*   src = (const int*)d_in[1];
    const int*   dst = (const int*)d_in[2];
    const float* WQ = (const float*)d_in[3];
    const float* bQ = (const float*)d_in[4];
    const float* WK = (const float*)d_in[5];
    const float* bK = (const float*)d_in[6];
    const float* WV = (const float*)d_in[7];
    const float* bV = (const float*)d_in[8];
    int N = in_sizes[0] / INDIM;
    int E = in_sizes[1];
    int NT = (N + 127) / 128;

    cudaFuncSetAttribute(qkv_hmma, cudaFuncAttributeMaxDynamicSharedMemorySize, SM_TOTAL);
    cudaFuncSetAttribute(conv_W, cudaFuncAttributeMaxDynamicSharedMemorySize, 128 * 132 * 4);

    cudaStream_t s2;
    cudaStreamCreateWithFlags(&s2, cudaStreamNonBlocking);
    cudaEvent_t evF, evJ;
    cudaEventCreateWithFlags(&evF, cudaEventDisableTiming);
    cudaEventCreateWithFlags(&evJ, cudaEventDisableTiming);

    cudaEventRecord(evF, 0);
    cudaStreamWaitEvent(s2, evF, 0);

    // --- s2: CSR chain (4 kernels) ---
    int E4 = (E + 3) / 4;
    int nb = (N + 1023) / 1024;
    hist_k<<<(E4 + 255) / 256, 256, 0, s2>>>(dst, E);
    scan_partial<<<nb, 1024, 0, s2>>>(N);
    scan_add<<<nb, 1024, 0, s2>>>(N, E);
    scatter_k<<<(E4 + 255) / 256, 256, 0, s2>>>(src, dst, E);
    cudaEventRecord(evJ, s2);

    // --- default stream: QKV chain ---
    conv_W<<<3, 256, 128 * 132 * 4>>>(WQ, WK, WV);
    qkv_hmma<<<NT, 256, SM_TOTAL>>>(h, bQ, bK, bV, N);

    cudaStreamWaitEvent(0, evJ, 0);
    gather_attn<<<(N + 7) / 8, 256>>>((float*)d_out, N);
}